// round 1
// baseline (speedup 1.0000x reference)
#include <cuda_runtime.h>
#include <math.h>

#define BB   8
#define TT   1024
#define DD   1024
#define HH   16
#define EE   64
#define FF   4096
#define BT   (BB*TT)   // 8192

// ---------------- scratch (device globals; no allocs allowed) ----------------
__device__ float g_xn [BT*DD];   // LN1 output
__device__ float g_q  [BT*DD];   // [B,H,T,E]
__device__ float g_k  [BT*DD];
__device__ float g_v  [BT*DD];
__device__ float g_att[BT*DD];   // concat heads [BT, D]
__device__ float g_x2 [BT*DD];   // after attn residual
__device__ float g_xn2[BT*DD];   // LN2 output
__device__ float g_h  [BT*FF];   // FFN hidden

// ---------------- LayerNorm: one block per row ----------------
__global__ void ln_kernel(const float* __restrict__ x, const float* __restrict__ g,
                          const float* __restrict__ b, float* __restrict__ y) {
    int row = blockIdx.x;
    int tid = threadIdx.x;                       // 256 threads, 4 elems each
    const float4* xr = (const float4*)(x + (size_t)row * DD);
    float4 v = xr[tid];
    float s  = v.x + v.y + v.z + v.w;
    float sq = v.x*v.x + v.y*v.y + v.z*v.z + v.w*v.w;
    #pragma unroll
    for (int m = 16; m >= 1; m >>= 1) {
        s  += __shfl_xor_sync(0xffffffffu, s,  m);
        sq += __shfl_xor_sync(0xffffffffu, sq, m);
    }
    __shared__ float ss[8], ssq[8];
    int wid = tid >> 5, lane = tid & 31;
    if (lane == 0) { ss[wid] = s; ssq[wid] = sq; }
    __syncthreads();
    s = 0.f; sq = 0.f;
    #pragma unroll
    for (int i = 0; i < 8; i++) { s += ss[i]; sq += ssq[i]; }
    float mu   = s * (1.0f / DD);
    float var  = sq * (1.0f / DD) - mu * mu;
    float rstd = rsqrtf(var + 1e-5f);
    float4 gg = ((const float4*)g)[tid];
    float4 bv = ((const float4*)b)[tid];
    float4 o;
    o.x = (v.x - mu) * rstd * gg.x + bv.x;
    o.y = (v.y - mu) * rstd * gg.y + bv.y;
    o.z = (v.z - mu) * rstd * gg.z + bv.z;
    o.w = (v.w - mu) * rstd * gg.w + bv.w;
    ((float4*)(y + (size_t)row * DD))[tid] = o;
}

// ---------------- classic 128x128x8 SGEMM, 8x8 per thread ----------------
// C[M,N] = A[M,K] @ B[K,N] (+bias[N]) (ReLU?) (+resid[M,N])
__global__ void sgemm128(const float* __restrict__ A, const float* __restrict__ Bm,
                         float* __restrict__ C, int M, int N, int K,
                         const float* __restrict__ bias,
                         const float* __restrict__ resid, int relu) {
    __shared__ float As[8][128];
    __shared__ float Bs[8][128];
    int tid = threadIdx.x;
    int tr = tid >> 4, tc = tid & 15;
    int rowBase = blockIdx.y * 128;
    int colBase = blockIdx.x * 128;

    float acc[8][8];
    #pragma unroll
    for (int i = 0; i < 8; i++)
        #pragma unroll
        for (int j = 0; j < 8; j++) acc[i][j] = 0.f;

    int am = tid >> 1;           // 0..127
    int ak = (tid & 1) * 4;      // 0 or 4
    int bk = tid >> 5;           // 0..7
    int bn = (tid & 31) * 4;     // 0..124
    const float* Aptr = A + (size_t)(rowBase + am) * K + ak;
    const float* Bptr = Bm + (size_t)bk * N + colBase + bn;

    for (int k0 = 0; k0 < K; k0 += 8) {
        float4 a4 = *(const float4*)(Aptr + k0);
        As[ak + 0][am] = a4.x; As[ak + 1][am] = a4.y;
        As[ak + 2][am] = a4.z; As[ak + 3][am] = a4.w;
        *(float4*)&Bs[bk][bn] = *(const float4*)(Bptr + (size_t)k0 * N);
        __syncthreads();
        #pragma unroll
        for (int k = 0; k < 8; k++) {
            float a[8], b[8];
            #pragma unroll
            for (int i = 0; i < 8; i++) a[i] = As[k][tr * 8 + i];
            #pragma unroll
            for (int j = 0; j < 8; j++) b[j] = Bs[k][tc * 8 + j];
            #pragma unroll
            for (int i = 0; i < 8; i++)
                #pragma unroll
                for (int j = 0; j < 8; j++) acc[i][j] = fmaf(a[i], b[j], acc[i][j]);
        }
        __syncthreads();
    }

    #pragma unroll
    for (int i = 0; i < 8; i++) {
        int r = rowBase + tr * 8 + i;
        #pragma unroll
        for (int j = 0; j < 8; j++) {
            int c = colBase + tc * 8 + j;
            float v = acc[i][j];
            if (bias)  v += bias[c];
            if (relu)  v = fmaxf(v, 0.f);
            if (resid) v += resid[(size_t)r * N + c];
            C[(size_t)r * N + c] = v;
        }
    }
}

// ---------------- per-head projection GEMM: [BT,D] @ [D,64] -> [B,H,T,E] ----
__global__ void qkv_gemm(const float* __restrict__ A, const float* __restrict__ W,
                         float* __restrict__ out) {
    __shared__ float As[8][128];
    __shared__ float Bs[8][64];
    int tid = threadIdx.x;
    int h = blockIdx.y;
    int rowBase = blockIdx.x * 128;
    int tr = tid >> 4, tc = tid & 15;    // 16x16 -> rows tr*8.., cols tc*4..

    float acc[8][4];
    #pragma unroll
    for (int i = 0; i < 8; i++)
        #pragma unroll
        for (int j = 0; j < 4; j++) acc[i][j] = 0.f;

    int am = tid >> 1, ak = (tid & 1) * 4;
    int bk = tid >> 5, bn = (tid & 31) * 2;
    const float* Aptr = A + (size_t)(rowBase + am) * DD + ak;
    const float* Wh = W + (size_t)h * DD * EE;

    for (int k0 = 0; k0 < DD; k0 += 8) {
        float4 a4 = *(const float4*)(Aptr + k0);
        As[ak + 0][am] = a4.x; As[ak + 1][am] = a4.y;
        As[ak + 2][am] = a4.z; As[ak + 3][am] = a4.w;
        *(float2*)&Bs[bk][bn] = *(const float2*)(Wh + (size_t)(k0 + bk) * EE + bn);
        __syncthreads();
        #pragma unroll
        for (int k = 0; k < 8; k++) {
            float a[8], b[4];
            #pragma unroll
            for (int i = 0; i < 8; i++) a[i] = As[k][tr * 8 + i];
            #pragma unroll
            for (int j = 0; j < 4; j++) b[j] = Bs[k][tc * 4 + j];
            #pragma unroll
            for (int i = 0; i < 8; i++)
                #pragma unroll
                for (int j = 0; j < 4; j++) acc[i][j] = fmaf(a[i], b[j], acc[i][j]);
        }
        __syncthreads();
    }

    #pragma unroll
    for (int i = 0; i < 8; i++) {
        int rowg = rowBase + tr * 8 + i;     // global token
        int bidx = rowg >> 10;
        int t    = rowg & 1023;
        #pragma unroll
        for (int j = 0; j < 4; j++) {
            int e = tc * 4 + j;
            out[(((size_t)bidx * HH + h) * TT + t) * EE + e] = acc[i][j];
        }
    }
}

// ---------------- flash-style causal attention ----------------
// grid: (T/64, B*H), block 256. smem: Q,K,V,P tiles (64x64, pitch 65)
#define APITCH 65
__global__ void flash_kernel() {
    extern __shared__ float sm[];
    float* Qs = sm;
    float* Ks = sm + 64 * APITCH;
    float* Vs = sm + 2 * 64 * APITCH;
    float* Ps = sm + 3 * 64 * APITCH;

    int tid = threadIdx.x;
    int qt = blockIdx.x;          // query tile 0..15
    int bh = blockIdx.y;          // 0..127
    const float* Q = g_q + (size_t)bh * TT * EE;
    const float* K = g_k + (size_t)bh * TT * EE;
    const float* V = g_v + (size_t)bh * TT * EE;

    int tr = tid >> 4, tc = tid & 15;
    int r0 = tr * 4, c0 = tc * 4;

    for (int i = tid; i < 64 * 64; i += 256) {
        int r = i >> 6, e = i & 63;
        Qs[r * APITCH + e] = Q[(size_t)(qt * 64 + r) * EE + e];
    }

    float m_run[4], l_run[4], acc[4][4];
    #pragma unroll
    for (int i = 0; i < 4; i++) {
        m_run[i] = -INFINITY; l_run[i] = 0.f;
        #pragma unroll
        for (int j = 0; j < 4; j++) acc[i][j] = 0.f;
    }

    const float scale = 0.125f;   // 1/sqrt(64)

    for (int kt = 0; kt <= qt; kt++) {
        __syncthreads();
        for (int i = tid; i < 64 * 64; i += 256) {
            int r = i >> 6, e = i & 63;
            Ks[r * APITCH + e] = K[(size_t)(kt * 64 + r) * EE + e];
            Vs[r * APITCH + e] = V[(size_t)(kt * 64 + r) * EE + e];
        }
        __syncthreads();

        float s[4][4];
        #pragma unroll
        for (int i = 0; i < 4; i++)
            #pragma unroll
            for (int j = 0; j < 4; j++) s[i][j] = 0.f;

        #pragma unroll 4
        for (int e = 0; e < 64; e++) {
            float qv[4], kv[4];
            #pragma unroll
            for (int i = 0; i < 4; i++) qv[i] = Qs[(r0 + i) * APITCH + e];
            #pragma unroll
            for (int j = 0; j < 4; j++) kv[j] = Ks[(c0 + j) * APITCH + e];
            #pragma unroll
            for (int i = 0; i < 4; i++)
                #pragma unroll
                for (int j = 0; j < 4; j++) s[i][j] = fmaf(qv[i], kv[j], s[i][j]);
        }

        #pragma unroll
        for (int i = 0; i < 4; i++) {
            int grow = qt * 64 + r0 + i;
            #pragma unroll
            for (int j = 0; j < 4; j++) {
                int gcol = kt * 64 + c0 + j;
                s[i][j] = (gcol <= grow) ? s[i][j] * scale : -1e30f;
            }
        }

        #pragma unroll
        for (int i = 0; i < 4; i++) {
            float mloc = fmaxf(fmaxf(s[i][0], s[i][1]), fmaxf(s[i][2], s[i][3]));
            #pragma unroll
            for (int m = 8; m >= 1; m >>= 1)
                mloc = fmaxf(mloc, __shfl_xor_sync(0xffffffffu, mloc, m));
            float mn = fmaxf(m_run[i], mloc);
            float f = __expf(m_run[i] - mn);
            m_run[i] = mn;
            float rs = 0.f;
            #pragma unroll
            for (int j = 0; j < 4; j++) { s[i][j] = __expf(s[i][j] - mn); rs += s[i][j]; }
            #pragma unroll
            for (int m = 8; m >= 1; m >>= 1)
                rs += __shfl_xor_sync(0xffffffffu, rs, m);
            l_run[i] = l_run[i] * f + rs;
            #pragma unroll
            for (int j = 0; j < 4; j++) acc[i][j] *= f;
        }

        #pragma unroll
        for (int i = 0; i < 4; i++)
            #pragma unroll
            for (int j = 0; j < 4; j++) Ps[(r0 + i) * APITCH + c0 + j] = s[i][j];
        __syncthreads();

        #pragma unroll 4
        for (int c = 0; c < 64; c++) {
            float pv[4], vv[4];
            #pragma unroll
            for (int i = 0; i < 4; i++) pv[i] = Ps[(r0 + i) * APITCH + c];
            #pragma unroll
            for (int j = 0; j < 4; j++) vv[j] = Vs[c * APITCH + c0 + j];
            #pragma unroll
            for (int i = 0; i < 4; i++)
                #pragma unroll
                for (int j = 0; j < 4; j++) acc[i][j] = fmaf(pv[i], vv[j], acc[i][j]);
        }
    }

    int b = bh >> 4, h = bh & 15;
    #pragma unroll
    for (int i = 0; i < 4; i++) {
        float inv = 1.f / l_run[i];
        size_t row = (size_t)b * TT + qt * 64 + r0 + i;
        #pragma unroll
        for (int j = 0; j < 4; j++)
            g_att[row * DD + h * EE + c0 + j] = acc[i][j] * inv;
    }
}

// ---------------- launch ----------------
extern "C" void kernel_launch(void* const* d_in, const int* in_sizes, int n_in,
                              void* d_out, int out_size) {
    (void)in_sizes; (void)n_in; (void)out_size;
    const float* x      = (const float*)d_in[0];
    const float* wq     = (const float*)d_in[1];
    const float* wk     = (const float*)d_in[2];
    const float* wv     = (const float*)d_in[3];
    const float* w_proj = (const float*)d_in[4];
    const float* b_proj = (const float*)d_in[5];
    const float* w1     = (const float*)d_in[6];
    const float* b1     = (const float*)d_in[7];
    const float* w2     = (const float*)d_in[8];
    const float* b2     = (const float*)d_in[9];
    const float* g1     = (const float*)d_in[10];
    const float* be1    = (const float*)d_in[11];
    const float* g2     = (const float*)d_in[12];
    const float* be2    = (const float*)d_in[13];
    float* out = (float*)d_out;

    float *p_xn, *p_q, *p_k, *p_v, *p_att, *p_x2, *p_xn2, *p_h;
    cudaGetSymbolAddress((void**)&p_xn,  g_xn);
    cudaGetSymbolAddress((void**)&p_q,   g_q);
    cudaGetSymbolAddress((void**)&p_k,   g_k);
    cudaGetSymbolAddress((void**)&p_v,   g_v);
    cudaGetSymbolAddress((void**)&p_att, g_att);
    cudaGetSymbolAddress((void**)&p_x2,  g_x2);
    cudaGetSymbolAddress((void**)&p_xn2, g_xn2);
    cudaGetSymbolAddress((void**)&p_h,   g_h);

    const int FLASH_SMEM = 4 * 64 * APITCH * sizeof(float);
    cudaFuncSetAttribute(flash_kernel, cudaFuncAttributeMaxDynamicSharedMemorySize, FLASH_SMEM);

    // 1. LN1
    ln_kernel<<<BT, 256>>>(x, g1, be1, p_xn);

    // 2. Q/K/V per-head projections
    dim3 qkvGrid(BT / 128, HH);
    qkv_gemm<<<qkvGrid, 256>>>(p_xn, wq, p_q);
    qkv_gemm<<<qkvGrid, 256>>>(p_xn, wk, p_k);
    qkv_gemm<<<qkvGrid, 256>>>(p_xn, wv, p_v);

    // 3. causal attention
    flash_kernel<<<dim3(TT / 64, BB * HH), 256, FLASH_SMEM>>>();

    // 4. output projection + bias + residual(xn)
    sgemm128<<<dim3(DD / 128, BT / 128), 256>>>(p_att, w_proj, p_x2,
                                                BT, DD, DD, b_proj, p_xn, 0);

    // 5. LN2
    ln_kernel<<<BT, 256>>>(p_x2, g2, be2, p_xn2);

    // 6. FFN1 (ReLU)
    sgemm128<<<dim3(FF / 128, BT / 128), 256>>>(p_xn2, w1, p_h,
                                                BT, FF, DD, b1, nullptr, 1);

    // 7. FFN2 + bias + residual(xn2) -> out
    sgemm128<<<dim3(DD / 128, BT / 128), 256>>>(p_h, w2, out,
                                                BT, DD, FF, b2, p_xn2, 0);
}

// round 2
// speedup vs baseline: 2.3508x; 2.3508x over previous
#include <cuda_runtime.h>
#include <math.h>
#include <stdint.h>

#define BB   8
#define TT   1024
#define DD   1024
#define HH   16
#define EE   64
#define FF   4096
#define BT   (BB*TT)   // 8192

// ---------------- scratch (device globals; no allocs allowed) ----------------
__device__ float g_xn  [BT*DD];    // LN1 output
__device__ float g_qkv [BT*3*DD];  // fused QKV: [BT][3072] (q|k|v, head-major in 64-chunks)
__device__ float g_wcat[DD*3*DD];  // [D][3072] concat of wq|wk|wv rearranged
__device__ float g_att [BT*DD];    // concat heads [BT, D]
__device__ float g_x2  [BT*DD];    // after attn residual
__device__ float g_xn2 [BT*DD];    // LN2 output
__device__ float g_h   [BT*FF];    // FFN hidden

// ---------------- helpers ----------------
__device__ __forceinline__ unsigned f2tf(float f) {
    unsigned u;
    asm("cvt.rna.tf32.f32 %0, %1;" : "=r"(u) : "f"(f));
    return u;
}

__device__ __forceinline__ void mma_tf32(float* d, const unsigned* a, unsigned b0, unsigned b1) {
    asm volatile(
        "mma.sync.aligned.m16n8k8.row.col.f32.tf32.tf32.f32 "
        "{%0,%1,%2,%3}, {%4,%5,%6,%7}, {%8,%9}, {%0,%1,%2,%3};\n"
        : "+f"(d[0]), "+f"(d[1]), "+f"(d[2]), "+f"(d[3])
        : "r"(a[0]), "r"(a[1]), "r"(a[2]), "r"(a[3]), "r"(b0), "r"(b1));
}

#define CP16(sm, gm) asm volatile("cp.async.ca.shared.global [%0], [%1], 16;\n" :: "r"(sm), "l"(gm))

// ---------------- LayerNorm: one block per row ----------------
__global__ void ln_kernel(const float* __restrict__ x, const float* __restrict__ g,
                          const float* __restrict__ b, float* __restrict__ y) {
    int row = blockIdx.x;
    int tid = threadIdx.x;                       // 256 threads, 4 elems each
    const float4* xr = (const float4*)(x + (size_t)row * DD);
    float4 v = xr[tid];
    float s  = v.x + v.y + v.z + v.w;
    float sq = v.x*v.x + v.y*v.y + v.z*v.z + v.w*v.w;
    #pragma unroll
    for (int m = 16; m >= 1; m >>= 1) {
        s  += __shfl_xor_sync(0xffffffffu, s,  m);
        sq += __shfl_xor_sync(0xffffffffu, sq, m);
    }
    __shared__ float ss[8], ssq[8];
    int wid = tid >> 5, lane = tid & 31;
    if (lane == 0) { ss[wid] = s; ssq[wid] = sq; }
    __syncthreads();
    s = 0.f; sq = 0.f;
    #pragma unroll
    for (int i = 0; i < 8; i++) { s += ss[i]; sq += ssq[i]; }
    float mu   = s * (1.0f / DD);
    float var  = sq * (1.0f / DD) - mu * mu;
    float rstd = rsqrtf(var + 1e-5f);
    float4 gg = ((const float4*)g)[tid];
    float4 bv = ((const float4*)b)[tid];
    float4 o;
    o.x = (v.x - mu) * rstd * gg.x + bv.x;
    o.y = (v.y - mu) * rstd * gg.y + bv.y;
    o.z = (v.z - mu) * rstd * gg.z + bv.z;
    o.w = (v.w - mu) * rstd * gg.w + bv.w;
    ((float4*)(y + (size_t)row * DD))[tid] = o;
}

// ---------------- weight concat: wcat[k][s*1024 + h*64 + e] = w_s[h][k][e] ----
__global__ void concat_w(const float* __restrict__ wq, const float* __restrict__ wk,
                         const float* __restrict__ wv, float* __restrict__ wcat) {
    int i = blockIdx.x * 256 + threadIdx.x;      // over D*3072/4 float4 chunks
    int idx4 = i * 4;
    int col  = idx4 % (3 * DD);
    int k    = idx4 / (3 * DD);
    int s    = col >> 10;
    int hc   = col & 1023;
    int h    = hc >> 6;
    int e    = hc & 63;
    const float* w = (s == 0) ? wq : (s == 1) ? wk : wv;
    float4 v = *(const float4*)&w[((size_t)h * DD + k) * EE + e];
    *(float4*)&wcat[(size_t)k * (3 * DD) + col] = v;
}

// ---------------- tf32 tensor-core GEMM: 128x128 tile, 8 warps, KBLK=16 ------
// C[M,N] = A[M,K] @ B[K,N] (+bias[N]) (ReLU?) (+resid[M,N])
#define KBLK   16
#define APITCHG 20     // A smem pitch (floats): 20 -> conflict-free frag reads
#define BPITCHG 136    // B smem pitch (floats): 136 -> conflict-free frag reads
#define ASTG   (128 * APITCHG)   // 2560 floats / stage
#define BSTG   (KBLK * BPITCHG)  // 2176 floats / stage

__global__ __launch_bounds__(256) void tgemm(const float* __restrict__ A,
                                             const float* __restrict__ B,
                                             float* __restrict__ C,
                                             int M, int N, int K,
                                             const float* __restrict__ bias,
                                             const float* __restrict__ resid,
                                             int relu) {
    __shared__ float As[2][ASTG];
    __shared__ float Bs[2][BSTG];

    int tid  = threadIdx.x;
    int warp = tid >> 5, lane = tid & 31;
    int wm = warp >> 1, wn = warp & 1;        // 4 x 2 warp grid
    int m0 = wm * 32,  n0 = wn * 64;          // warp tile 32x64
    int rowBase = blockIdx.y * 128;
    int colBase = blockIdx.x * 128;

    // global load mapping
    int am  = tid >> 1;          // 0..127
    int akq = (tid & 1) * 8;     // 0 or 8 (two float4 each)
    int bk  = tid >> 4;          // 0..15
    int bn  = (tid & 15) * 8;    // 0..120 (two float4 each)
    const float* Ag = A + (size_t)(rowBase + am) * K + akq;
    const float* Bg = B + (size_t)bk * N + colBase + bn;

    uint32_t sA = (uint32_t)__cvta_generic_to_shared(&As[0][0]);
    uint32_t sB = (uint32_t)__cvta_generic_to_shared(&Bs[0][0]);
    uint32_t aOff0 = (am * APITCHG + akq) * 4;
    uint32_t bOff0 = (bk * BPITCHG + bn) * 4;

    float acc[2][8][4];
    #pragma unroll
    for (int mi = 0; mi < 2; mi++)
        #pragma unroll
        for (int nj = 0; nj < 8; nj++)
            #pragma unroll
            for (int t = 0; t < 4; t++) acc[mi][nj][t] = 0.f;

    int nk = K / KBLK;

    // prologue: stage 0
    {
        const float* ag = Ag;
        const float* bg = Bg;
        CP16(sA + aOff0,      ag);
        CP16(sA + aOff0 + 16, ag + 4);
        CP16(sB + bOff0,      bg);
        CP16(sB + bOff0 + 16, bg + 4);
        asm volatile("cp.async.commit_group;\n");
    }

    for (int i = 0; i < nk; i++) {
        if (i + 1 < nk) {
            int s = (i + 1) & 1;
            const float* ag = Ag + (i + 1) * KBLK;
            const float* bg = Bg + (size_t)(i + 1) * KBLK * N;
            uint32_t sa = sA + s * (ASTG * 4);
            uint32_t sb = sB + s * (BSTG * 4);
            CP16(sa + aOff0,      ag);
            CP16(sa + aOff0 + 16, ag + 4);
            CP16(sb + bOff0,      bg);
            CP16(sb + bOff0 + 16, bg + 4);
            asm volatile("cp.async.commit_group;\n");
            asm volatile("cp.async.wait_group 1;\n");
        } else {
            asm volatile("cp.async.wait_group 0;\n");
        }
        __syncthreads();

        const float* as = As[i & 1];
        const float* bs = Bs[i & 1];
        #pragma unroll
        for (int ks = 0; ks < 2; ks++) {
            int kk = ks * 8;
            unsigned af[2][4];
            #pragma unroll
            for (int mi = 0; mi < 2; mi++) {
                int r = m0 + mi * 16 + (lane >> 2);
                int c = kk + (lane & 3);
                af[mi][0] = f2tf(as[r * APITCHG + c]);
                af[mi][1] = f2tf(as[(r + 8) * APITCHG + c]);
                af[mi][2] = f2tf(as[r * APITCHG + c + 4]);
                af[mi][3] = f2tf(as[(r + 8) * APITCHG + c + 4]);
            }
            #pragma unroll
            for (int nj = 0; nj < 8; nj++) {
                int cn = n0 + nj * 8 + (lane >> 2);
                unsigned b0 = f2tf(bs[(kk + (lane & 3)) * BPITCHG + cn]);
                unsigned b1 = f2tf(bs[(kk + (lane & 3) + 4) * BPITCHG + cn]);
                mma_tf32(acc[0][nj], af[0], b0, b1);
                mma_tf32(acc[1][nj], af[1], b0, b1);
            }
        }
        __syncthreads();
    }

    // epilogue
    #pragma unroll
    for (int mi = 0; mi < 2; mi++) {
        int r = rowBase + m0 + mi * 16 + (lane >> 2);
        #pragma unroll
        for (int nj = 0; nj < 8; nj++) {
            int c = colBase + n0 + nj * 8 + (lane & 3) * 2;
            float v0 = acc[mi][nj][0];
            float v1 = acc[mi][nj][1];
            float v2 = acc[mi][nj][2];
            float v3 = acc[mi][nj][3];
            if (bias)  { v0 += bias[c]; v1 += bias[c + 1]; v2 += bias[c]; v3 += bias[c + 1]; }
            if (relu)  { v0 = fmaxf(v0, 0.f); v1 = fmaxf(v1, 0.f);
                         v2 = fmaxf(v2, 0.f); v3 = fmaxf(v3, 0.f); }
            if (resid) {
                const float* rr0 = resid + (size_t)r * N + c;
                const float* rr1 = resid + (size_t)(r + 8) * N + c;
                v0 += rr0[0]; v1 += rr0[1]; v2 += rr1[0]; v3 += rr1[1];
            }
            float2 o0 = make_float2(v0, v1);
            float2 o1 = make_float2(v2, v3);
            *(float2*)&C[(size_t)r * N + c]       = o0;
            *(float2*)&C[(size_t)(r + 8) * N + c] = o1;
        }
    }
}

// ---------------- flash-style causal attention ----------------
// grid: (T/64, B*H), block 256. smem: Q,K,V,P tiles (64x64, pitch 65)
#define APITCH 65
__global__ void flash_kernel(const float* __restrict__ qkv, float* __restrict__ attout) {
    extern __shared__ float sm[];
    float* Qs = sm;
    float* Ks = sm + 64 * APITCH;
    float* Vs = sm + 2 * 64 * APITCH;
    float* Ps = sm + 3 * 64 * APITCH;

    int tid = threadIdx.x;
    int qt = blockIdx.x;          // query tile 0..15
    int bh = blockIdx.y;          // 0..127
    int b = bh >> 4, h = bh & 15;
    const int STR = 3 * DD;       // 3072
    const float* Q = qkv + (size_t)b * TT * STR + h * EE;
    const float* K = Q + DD;
    const float* V = Q + 2 * DD;

    int tr = tid >> 4, tc = tid & 15;
    int r0 = tr * 4, c0 = tc * 4;

    for (int i = tid; i < 64 * 16; i += 256) {
        int r = i >> 4, e4 = (i & 15) * 4;
        float4 v = *(const float4*)&Q[(size_t)(qt * 64 + r) * STR + e4];
        Qs[r * APITCH + e4 + 0] = v.x; Qs[r * APITCH + e4 + 1] = v.y;
        Qs[r * APITCH + e4 + 2] = v.z; Qs[r * APITCH + e4 + 3] = v.w;
    }

    float m_run[4], l_run[4], acc[4][4];
    #pragma unroll
    for (int i = 0; i < 4; i++) {
        m_run[i] = -INFINITY; l_run[i] = 0.f;
        #pragma unroll
        for (int j = 0; j < 4; j++) acc[i][j] = 0.f;
    }

    const float scale = 0.125f;   // 1/sqrt(64)

    for (int kt = 0; kt <= qt; kt++) {
        __syncthreads();
        for (int i = tid; i < 64 * 16; i += 256) {
            int r = i >> 4, e4 = (i & 15) * 4;
            float4 kv = *(const float4*)&K[(size_t)(kt * 64 + r) * STR + e4];
            float4 vv = *(const float4*)&V[(size_t)(kt * 64 + r) * STR + e4];
            Ks[r * APITCH + e4 + 0] = kv.x; Ks[r * APITCH + e4 + 1] = kv.y;
            Ks[r * APITCH + e4 + 2] = kv.z; Ks[r * APITCH + e4 + 3] = kv.w;
            Vs[r * APITCH + e4 + 0] = vv.x; Vs[r * APITCH + e4 + 1] = vv.y;
            Vs[r * APITCH + e4 + 2] = vv.z; Vs[r * APITCH + e4 + 3] = vv.w;
        }
        __syncthreads();

        float s[4][4];
        #pragma unroll
        for (int i = 0; i < 4; i++)
            #pragma unroll
            for (int j = 0; j < 4; j++) s[i][j] = 0.f;

        #pragma unroll 4
        for (int e = 0; e < 64; e++) {
            float qv[4], kv[4];
            #pragma unroll
            for (int i = 0; i < 4; i++) qv[i] = Qs[(r0 + i) * APITCH + e];
            #pragma unroll
            for (int j = 0; j < 4; j++) kv[j] = Ks[(c0 + j) * APITCH + e];
            #pragma unroll
            for (int i = 0; i < 4; i++)
                #pragma unroll
                for (int j = 0; j < 4; j++) s[i][j] = fmaf(qv[i], kv[j], s[i][j]);
        }

        #pragma unroll
        for (int i = 0; i < 4; i++) {
            int grow = qt * 64 + r0 + i;
            #pragma unroll
            for (int j = 0; j < 4; j++) {
                int gcol = kt * 64 + c0 + j;
                s[i][j] = (gcol <= grow) ? s[i][j] * scale : -1e30f;
            }
        }

        #pragma unroll
        for (int i = 0; i < 4; i++) {
            float mloc = fmaxf(fmaxf(s[i][0], s[i][1]), fmaxf(s[i][2], s[i][3]));
            #pragma unroll
            for (int m = 8; m >= 1; m >>= 1)
                mloc = fmaxf(mloc, __shfl_xor_sync(0xffffffffu, mloc, m));
            float mn = fmaxf(m_run[i], mloc);
            float f = __expf(m_run[i] - mn);
            m_run[i] = mn;
            float rs = 0.f;
            #pragma unroll
            for (int j = 0; j < 4; j++) { s[i][j] = __expf(s[i][j] - mn); rs += s[i][j]; }
            #pragma unroll
            for (int m = 8; m >= 1; m >>= 1)
                rs += __shfl_xor_sync(0xffffffffu, rs, m);
            l_run[i] = l_run[i] * f + rs;
            #pragma unroll
            for (int j = 0; j < 4; j++) acc[i][j] *= f;
        }

        #pragma unroll
        for (int i = 0; i < 4; i++)
            #pragma unroll
            for (int j = 0; j < 4; j++) Ps[(r0 + i) * APITCH + c0 + j] = s[i][j];
        __syncthreads();

        #pragma unroll 4
        for (int c = 0; c < 64; c++) {
            float pv[4], vv[4];
            #pragma unroll
            for (int i = 0; i < 4; i++) pv[i] = Ps[(r0 + i) * APITCH + c];
            #pragma unroll
            for (int j = 0; j < 4; j++) vv[j] = Vs[c * APITCH + c0 + j];
            #pragma unroll
            for (int i = 0; i < 4; i++)
                #pragma unroll
                for (int j = 0; j < 4; j++) acc[i][j] = fmaf(pv[i], vv[j], acc[i][j]);
        }
    }

    #pragma unroll
    for (int i = 0; i < 4; i++) {
        float inv = 1.f / l_run[i];
        size_t row = (size_t)b * TT + qt * 64 + r0 + i;
        #pragma unroll
        for (int j = 0; j < 4; j++)
            attout[row * DD + h * EE + c0 + j] = acc[i][j] * inv;
    }
}

// ---------------- launch ----------------
extern "C" void kernel_launch(void* const* d_in, const int* in_sizes, int n_in,
                              void* d_out, int out_size) {
    (void)in_sizes; (void)n_in; (void)out_size;
    const float* x      = (const float*)d_in[0];
    const float* wq     = (const float*)d_in[1];
    const float* wk     = (const float*)d_in[2];
    const float* wv     = (const float*)d_in[3];
    const float* w_proj = (const float*)d_in[4];
    const float* b_proj = (const float*)d_in[5];
    const float* w1     = (const float*)d_in[6];
    const float* b1     = (const float*)d_in[7];
    const float* w2     = (const float*)d_in[8];
    const float* b2     = (const float*)d_in[9];
    const float* g1     = (const float*)d_in[10];
    const float* be1    = (const float*)d_in[11];
    const float* g2     = (const float*)d_in[12];
    const float* be2    = (const float*)d_in[13];
    float* out = (float*)d_out;

    float *p_xn, *p_qkv, *p_wcat, *p_att, *p_x2, *p_xn2, *p_h;
    cudaGetSymbolAddress((void**)&p_xn,   g_xn);
    cudaGetSymbolAddress((void**)&p_qkv,  g_qkv);
    cudaGetSymbolAddress((void**)&p_wcat, g_wcat);
    cudaGetSymbolAddress((void**)&p_att,  g_att);
    cudaGetSymbolAddress((void**)&p_x2,   g_x2);
    cudaGetSymbolAddress((void**)&p_xn2,  g_xn2);
    cudaGetSymbolAddress((void**)&p_h,    g_h);

    const int FLASH_SMEM = 4 * 64 * APITCH * sizeof(float);
    cudaFuncSetAttribute(flash_kernel, cudaFuncAttributeMaxDynamicSharedMemorySize, FLASH_SMEM);

    // 0. concat QKV weights into [D][3072]
    concat_w<<<(DD * 3 * DD / 4) / 256, 256>>>(wq, wk, wv, p_wcat);

    // 1. LN1
    ln_kernel<<<BT, 256>>>(x, g1, be1, p_xn);

    // 2. fused QKV projection: [8192,1024] @ [1024,3072]
    tgemm<<<dim3(3 * DD / 128, BT / 128), 256>>>(p_xn, p_wcat, p_qkv,
                                                 BT, 3 * DD, DD, nullptr, nullptr, 0);

    // 3. causal attention
    flash_kernel<<<dim3(TT / 64, BB * HH), 256, FLASH_SMEM>>>(p_qkv, p_att);

    // 4. output projection + bias + residual(xn)
    tgemm<<<dim3(DD / 128, BT / 128), 256>>>(p_att, w_proj, p_x2,
                                             BT, DD, DD, b_proj, p_xn, 0);

    // 5. LN2
    ln_kernel<<<BT, 256>>>(p_x2, g2, be2, p_xn2);

    // 6. FFN1 (ReLU)
    tgemm<<<dim3(FF / 128, BT / 128), 256>>>(p_xn2, w1, p_h,
                                             BT, FF, DD, b1, nullptr, 1);

    // 7. FFN2 + bias + residual(xn2) -> out
    tgemm<<<dim3(DD / 128, BT / 128), 256>>>(p_h, w2, out,
                                             BT, DD, FF, b2, p_xn2, 0);
}

// round 4
// speedup vs baseline: 2.8517x; 1.2131x over previous
#include <cuda_runtime.h>
#include <math.h>
#include <stdint.h>

#define BB   8
#define TT   1024
#define DD   1024
#define HH   16
#define EE   64
#define FF   4096
#define BT   (BB*TT)   // 8192

// ---------------- scratch (device globals; no allocs allowed) ----------------
__device__ float g_xn  [BT*DD];    // LN1 exact (residual for proj)
__device__ float g_xnr [BT*DD];    // LN1 tf32-rounded (GEMM A)
__device__ float g_qkv [BT*3*DD];  // fused QKV (tf32-rounded)
__device__ float g_wcat[DD*3*DD];  // concat wq|wk|wv (tf32-rounded)
__device__ float g_att [BT*DD];    // attention out (tf32-rounded)
__device__ float g_x2  [BT*DD];    // after attn residual (exact)
__device__ float g_xn2 [BT*DD];    // LN2 exact (residual for FFN2)
__device__ float g_xn2r[BT*DD];    // LN2 rounded (GEMM A)
__device__ float g_h   [BT*FF];    // FFN hidden (tf32-rounded)
__device__ float g_wpr [DD*DD];    // w_proj rounded
__device__ float g_w1r [DD*FF];    // w1 rounded
__device__ float g_w2r [FF*DD];    // w2 rounded

// ---------------- helpers ----------------
__device__ __forceinline__ unsigned f2tf(float f) {
    unsigned u;
    asm("cvt.rna.tf32.f32 %0, %1;" : "=r"(u) : "f"(f));
    return u;
}
__device__ __forceinline__ float tff(float f) { return __uint_as_float(f2tf(f)); }

__device__ __forceinline__ void mma_tf32(float* d, const unsigned* a, unsigned b0, unsigned b1) {
    asm volatile(
        "mma.sync.aligned.m16n8k8.row.col.f32.tf32.tf32.f32 "
        "{%0,%1,%2,%3}, {%4,%5,%6,%7}, {%8,%9}, {%0,%1,%2,%3};\n"
        : "+f"(d[0]), "+f"(d[1]), "+f"(d[2]), "+f"(d[3])
        : "r"(a[0]), "r"(a[1]), "r"(a[2]), "r"(a[3]), "r"(b0), "r"(b1));
}

#define CP16(sm, gm) asm volatile("cp.async.ca.shared.global [%0], [%1], 16;\n" :: "r"(sm), "l"(gm))

// ---------------- elementwise tf32 rounding ----------------
__global__ void round_w(const float* __restrict__ in, float* __restrict__ out) {
    int i = (blockIdx.x * 256 + threadIdx.x) * 4;
    float4 v = *(const float4*)(in + i);
    v.x = tff(v.x); v.y = tff(v.y); v.z = tff(v.z); v.w = tff(v.w);
    *(float4*)(out + i) = v;
}

// ---------------- LayerNorm: exact + rounded outputs ----------------
__global__ void ln_kernel(const float* __restrict__ x, const float* __restrict__ g,
                          const float* __restrict__ b, float* __restrict__ y,
                          float* __restrict__ yr) {
    int row = blockIdx.x;
    int tid = threadIdx.x;
    const float4* xr = (const float4*)(x + (size_t)row * DD);
    float4 v = xr[tid];
    float s  = v.x + v.y + v.z + v.w;
    float sq = v.x*v.x + v.y*v.y + v.z*v.z + v.w*v.w;
    #pragma unroll
    for (int m = 16; m >= 1; m >>= 1) {
        s  += __shfl_xor_sync(0xffffffffu, s,  m);
        sq += __shfl_xor_sync(0xffffffffu, sq, m);
    }
    __shared__ float ss[8], ssq[8];
    int wid = tid >> 5, lane = tid & 31;
    if (lane == 0) { ss[wid] = s; ssq[wid] = sq; }
    __syncthreads();
    s = 0.f; sq = 0.f;
    #pragma unroll
    for (int i = 0; i < 8; i++) { s += ss[i]; sq += ssq[i]; }
    float mu   = s * (1.0f / DD);
    float var  = sq * (1.0f / DD) - mu * mu;
    float rstd = rsqrtf(var + 1e-5f);
    float4 gg = ((const float4*)g)[tid];
    float4 bv = ((const float4*)b)[tid];
    float4 o;
    o.x = (v.x - mu) * rstd * gg.x + bv.x;
    o.y = (v.y - mu) * rstd * gg.y + bv.y;
    o.z = (v.z - mu) * rstd * gg.z + bv.z;
    o.w = (v.w - mu) * rstd * gg.w + bv.w;
    ((float4*)(y + (size_t)row * DD))[tid] = o;
    float4 r;
    r.x = tff(o.x); r.y = tff(o.y); r.z = tff(o.z); r.w = tff(o.w);
    ((float4*)(yr + (size_t)row * DD))[tid] = r;
}

// ---------------- weight concat + round ----------------
__global__ void concat_w(const float* __restrict__ wq, const float* __restrict__ wk,
                         const float* __restrict__ wv, float* __restrict__ wcat) {
    int i = blockIdx.x * 256 + threadIdx.x;
    int idx4 = i * 4;
    int col  = idx4 % (3 * DD);
    int k    = idx4 / (3 * DD);
    int s    = col >> 10;
    int hc   = col & 1023;
    int h    = hc >> 6;
    int e    = hc & 63;
    const float* w = (s == 0) ? wq : (s == 1) ? wk : wv;
    float4 v = *(const float4*)&w[((size_t)h * DD + k) * EE + e];
    v.x = tff(v.x); v.y = tff(v.y); v.z = tff(v.z); v.w = tff(v.w);
    *(float4*)&wcat[(size_t)k * (3 * DD) + col] = v;
}

// ---------------- tf32 GEMM: 128x128 tile, 8 warps, KBLK=16, no in-loop cvt --
#define KBLK   16
#define APITCHG 20
#define BPITCHG 136
#define ASTG   (128 * APITCHG)
#define BSTG   (KBLK * BPITCHG)

__global__ __launch_bounds__(256) void tgemm(const float* __restrict__ A,
                                             const float* __restrict__ B,
                                             float* __restrict__ C,
                                             int M, int N, int K,
                                             const float* __restrict__ bias,
                                             const float* __restrict__ resid,
                                             int relu, int rnd) {
    __shared__ float As[2][ASTG];
    __shared__ float Bs[2][BSTG];

    int tid  = threadIdx.x;
    int warp = tid >> 5, lane = tid & 31;
    int wm = warp >> 1, wn = warp & 1;
    int m0 = wm * 32,  n0 = wn * 64;
    int rowBase = blockIdx.y * 128;
    int colBase = blockIdx.x * 128;

    int am  = tid >> 1;
    int akq = (tid & 1) * 8;
    int bk  = tid >> 4;
    int bn  = (tid & 15) * 8;
    const float* Ag = A + (size_t)(rowBase + am) * K + akq;
    const float* Bg = B + (size_t)bk * N + colBase + bn;

    uint32_t sA = (uint32_t)__cvta_generic_to_shared(&As[0][0]);
    uint32_t sB = (uint32_t)__cvta_generic_to_shared(&Bs[0][0]);
    uint32_t aOff0 = (am * APITCHG + akq) * 4;
    uint32_t bOff0 = (bk * BPITCHG + bn) * 4;

    float acc[2][8][4];
    #pragma unroll
    for (int mi = 0; mi < 2; mi++)
        #pragma unroll
        for (int nj = 0; nj < 8; nj++)
            #pragma unroll
            for (int t = 0; t < 4; t++) acc[mi][nj][t] = 0.f;

    int nk = K / KBLK;

    {
        CP16(sA + aOff0,      Ag);
        CP16(sA + aOff0 + 16, Ag + 4);
        CP16(sB + bOff0,      Bg);
        CP16(sB + bOff0 + 16, Bg + 4);
        asm volatile("cp.async.commit_group;\n");
    }

    for (int i = 0; i < nk; i++) {
        if (i + 1 < nk) {
            int s = (i + 1) & 1;
            const float* ag = Ag + (i + 1) * KBLK;
            const float* bg = Bg + (size_t)(i + 1) * KBLK * N;
            uint32_t sa = sA + s * (ASTG * 4);
            uint32_t sb = sB + s * (BSTG * 4);
            CP16(sa + aOff0,      ag);
            CP16(sa + aOff0 + 16, ag + 4);
            CP16(sb + bOff0,      bg);
            CP16(sb + bOff0 + 16, bg + 4);
            asm volatile("cp.async.commit_group;\n");
            asm volatile("cp.async.wait_group 1;\n");
        } else {
            asm volatile("cp.async.wait_group 0;\n");
        }
        __syncthreads();

        const unsigned* as = (const unsigned*)As[i & 1];
        const unsigned* bs = (const unsigned*)Bs[i & 1];
        #pragma unroll
        for (int ks = 0; ks < 2; ks++) {
            int kk = ks * 8;
            unsigned af[2][4];
            #pragma unroll
            for (int mi = 0; mi < 2; mi++) {
                int r = m0 + mi * 16 + (lane >> 2);
                int c = kk + (lane & 3);
                af[mi][0] = as[r * APITCHG + c];
                af[mi][1] = as[(r + 8) * APITCHG + c];
                af[mi][2] = as[r * APITCHG + c + 4];
                af[mi][3] = as[(r + 8) * APITCHG + c + 4];
            }
            #pragma unroll
            for (int nj = 0; nj < 8; nj++) {
                int cn = n0 + nj * 8 + (lane >> 2);
                unsigned b0 = bs[(kk + (lane & 3)) * BPITCHG + cn];
                unsigned b1 = bs[(kk + (lane & 3) + 4) * BPITCHG + cn];
                mma_tf32(acc[0][nj], af[0], b0, b1);
                mma_tf32(acc[1][nj], af[1], b0, b1);
            }
        }
        __syncthreads();
    }

    #pragma unroll
    for (int mi = 0; mi < 2; mi++) {
        int r = rowBase + m0 + mi * 16 + (lane >> 2);
        #pragma unroll
        for (int nj = 0; nj < 8; nj++) {
            int c = colBase + n0 + nj * 8 + (lane & 3) * 2;
            float v0 = acc[mi][nj][0];
            float v1 = acc[mi][nj][1];
            float v2 = acc[mi][nj][2];
            float v3 = acc[mi][nj][3];
            if (bias)  { v0 += bias[c]; v1 += bias[c + 1]; v2 += bias[c]; v3 += bias[c + 1]; }
            if (relu)  { v0 = fmaxf(v0, 0.f); v1 = fmaxf(v1, 0.f);
                         v2 = fmaxf(v2, 0.f); v3 = fmaxf(v3, 0.f); }
            if (resid) {
                const float* rr0 = resid + (size_t)r * N + c;
                const float* rr1 = resid + (size_t)(r + 8) * N + c;
                v0 += rr0[0]; v1 += rr0[1]; v2 += rr1[0]; v3 += rr1[1];
            }
            if (rnd) { v0 = tff(v0); v1 = tff(v1); v2 = tff(v2); v3 = tff(v3); }
            *(float2*)&C[(size_t)r * N + c]       = make_float2(v0, v1);
            *(float2*)&C[(size_t)(r + 8) * N + c] = make_float2(v2, v3);
        }
    }
}

// ---------------- tensor-core flash attention (compensated PV) ----------------
// grid (T/128, B*H), 256 threads (8 warps x 16 q-rows). K/V tiles 64, cp.async x2.
#define FP 72
#define KTILE_F (64 * FP)
__global__ __launch_bounds__(256) void flash_kernel(const float* __restrict__ qkv,
                                                    float* __restrict__ attout) {
    extern __shared__ float sm[];
    float* KsBase = sm;                     // 2 stages of 64*FP
    float* VsBase = sm + 2 * KTILE_F;       // 2 stages of 64*FP
    float* Phi    = sm + 4 * KTILE_F;       // 128*FP (Q staging, then P hi)
    float* Plo    = sm + 4 * KTILE_F + 128 * FP;  // 128*FP (P lo)

    int tid = threadIdx.x, warp = tid >> 5, lane = tid & 31;
    int qt = blockIdx.x;               // 0..7
    int bh = blockIdx.y;
    int b = bh >> 4, h = bh & 15;
    const float* Qg = qkv + (size_t)b * TT * (3 * DD) + h * EE;
    const float* Kg = Qg + DD;
    const float* Vg = Qg + 2 * DD;

    // stage Q tile (128x64) -> Phi -> register fragments (values already tf32)
    for (int i = tid; i < 128 * 16; i += 256) {
        int r = i >> 4, c4 = (i & 15) * 4;
        float4 v = *(const float4*)&Qg[(size_t)(qt * 128 + r) * (3 * DD) + c4];
        Phi[r * FP + c4 + 0] = v.x; Phi[r * FP + c4 + 1] = v.y;
        Phi[r * FP + c4 + 2] = v.z; Phi[r * FP + c4 + 3] = v.w;
    }
    __syncthreads();
    unsigned qf[8][4];
    {
        const unsigned* Pu = (const unsigned*)Phi;
        int r = warp * 16 + (lane >> 2);
        #pragma unroll
        for (int k8 = 0; k8 < 8; k8++) {
            int c = k8 * 8 + (lane & 3);
            qf[k8][0] = Pu[r * FP + c];
            qf[k8][1] = Pu[(r + 8) * FP + c];
            qf[k8][2] = Pu[r * FP + c + 4];
            qf[k8][3] = Pu[(r + 8) * FP + c + 4];
        }
    }
    __syncthreads();

    uint32_t sK = (uint32_t)__cvta_generic_to_shared(KsBase);
    uint32_t sV = (uint32_t)__cvta_generic_to_shared(VsBase);
    int nkt = 2 * qt + 2;

    // prefetch kt=0 into stage 0
    for (int i = tid; i < 64 * 16; i += 256) {
        int r = i >> 4, c4 = (i & 15) * 4;
        uint32_t off = (uint32_t)(r * FP + c4) * 4;
        CP16(sK + off, &Kg[(size_t)r * (3 * DD) + c4]);
        CP16(sV + off, &Vg[(size_t)r * (3 * DD) + c4]);
    }
    asm volatile("cp.async.commit_group;\n");

    float m0r = -1e30f, m1r = -1e30f, l0 = 0.f, l1 = 0.f;
    float o[8][4];
    #pragma unroll
    for (int nj = 0; nj < 8; nj++)
        #pragma unroll
        for (int t = 0; t < 4; t++) o[nj][t] = 0.f;

    int grow0 = qt * 128 + warp * 16 + (lane >> 2);
    const float scale = 0.125f;

    for (int kt = 0; kt < nkt; kt++) {
        if (kt + 1 < nkt) {
            int st = (kt + 1) & 1;
            for (int i = tid; i < 64 * 16; i += 256) {
                int r = i >> 4, c4 = (i & 15) * 4;
                uint32_t off = (uint32_t)(st * KTILE_F + r * FP + c4) * 4;
                CP16(sK + off, &Kg[(size_t)((kt + 1) * 64 + r) * (3 * DD) + c4]);
                CP16(sV + off, &Vg[(size_t)((kt + 1) * 64 + r) * (3 * DD) + c4]);
            }
            asm volatile("cp.async.commit_group;\n");
            asm volatile("cp.async.wait_group 1;\n");
        } else {
            asm volatile("cp.async.wait_group 0;\n");
        }
        __syncthreads();

        const unsigned* Ku = (const unsigned*)(KsBase + (kt & 1) * KTILE_F);
        const unsigned* Vu = (const unsigned*)(VsBase + (kt & 1) * KTILE_F);

        // S = Q @ K^T  (q,k stored tf32-rounded -> conversion lossless -> exact)
        float s[8][4];
        #pragma unroll
        for (int nj = 0; nj < 8; nj++)
            #pragma unroll
            for (int t = 0; t < 4; t++) s[nj][t] = 0.f;

        #pragma unroll
        for (int k8 = 0; k8 < 8; k8++) {
            #pragma unroll
            for (int nj = 0; nj < 8; nj++) {
                int key = nj * 8 + (lane >> 2);
                unsigned b0 = Ku[key * FP + k8 * 8 + (lane & 3)];
                unsigned b1 = Ku[key * FP + k8 * 8 + (lane & 3) + 4];
                mma_tf32(s[nj], qf[k8], b0, b1);
            }
        }

        // scale + causal mask (only diagonal tiles need masking)
        bool diag = (kt >= 2 * qt);
        #pragma unroll
        for (int nj = 0; nj < 8; nj++) {
            s[nj][0] *= scale; s[nj][1] *= scale;
            s[nj][2] *= scale; s[nj][3] *= scale;
            if (diag) {
                int gc = kt * 64 + nj * 8 + 2 * (lane & 3);
                if (gc     > grow0)     s[nj][0] = -1e30f;
                if (gc + 1 > grow0)     s[nj][1] = -1e30f;
                if (gc     > grow0 + 8) s[nj][2] = -1e30f;
                if (gc + 1 > grow0 + 8) s[nj][3] = -1e30f;
            }
        }

        // online softmax (rows grow0: c0,c1 | grow0+8: c2,c3)
        float mx0 = -1e30f, mx1 = -1e30f;
        #pragma unroll
        for (int nj = 0; nj < 8; nj++) {
            mx0 = fmaxf(mx0, fmaxf(s[nj][0], s[nj][1]));
            mx1 = fmaxf(mx1, fmaxf(s[nj][2], s[nj][3]));
        }
        mx0 = fmaxf(mx0, __shfl_xor_sync(0xffffffffu, mx0, 1));
        mx0 = fmaxf(mx0, __shfl_xor_sync(0xffffffffu, mx0, 2));
        mx1 = fmaxf(mx1, __shfl_xor_sync(0xffffffffu, mx1, 1));
        mx1 = fmaxf(mx1, __shfl_xor_sync(0xffffffffu, mx1, 2));
        float mn0 = fmaxf(m0r, mx0), mn1 = fmaxf(m1r, mx1);
        float f0 = __expf(m0r - mn0), f1 = __expf(m1r - mn1);
        m0r = mn0; m1r = mn1;
        float rs0 = 0.f, rs1 = 0.f;
        #pragma unroll
        for (int nj = 0; nj < 8; nj++) {
            s[nj][0] = __expf(s[nj][0] - mn0); rs0 += s[nj][0];
            s[nj][1] = __expf(s[nj][1] - mn0); rs0 += s[nj][1];
            s[nj][2] = __expf(s[nj][2] - mn1); rs1 += s[nj][2];
            s[nj][3] = __expf(s[nj][3] - mn1); rs1 += s[nj][3];
        }
        rs0 += __shfl_xor_sync(0xffffffffu, rs0, 1);
        rs0 += __shfl_xor_sync(0xffffffffu, rs0, 2);
        rs1 += __shfl_xor_sync(0xffffffffu, rs1, 1);
        rs1 += __shfl_xor_sync(0xffffffffu, rs1, 2);
        l0 = l0 * f0 + rs0;
        l1 = l1 * f1 + rs1;
        #pragma unroll
        for (int nj = 0; nj < 8; nj++) {
            o[nj][0] *= f0; o[nj][1] *= f0;
            o[nj][2] *= f1; o[nj][3] *= f1;
        }

        // store P split hi/lo — each warp only touches its own 16 rows
        {
            int pr = warp * 16 + (lane >> 2);
            #pragma unroll
            for (int nj = 0; nj < 8; nj++) {
                int c = nj * 8 + 2 * (lane & 3);
                float h0 = tff(s[nj][0]), h1 = tff(s[nj][1]);
                float h2 = tff(s[nj][2]), h3 = tff(s[nj][3]);
                *(float2*)&Phi[pr * FP + c]       = make_float2(h0, h1);
                *(float2*)&Phi[(pr + 8) * FP + c] = make_float2(h2, h3);
                *(float2*)&Plo[pr * FP + c]       = make_float2(tff(s[nj][0] - h0), tff(s[nj][1] - h1));
                *(float2*)&Plo[(pr + 8) * FP + c] = make_float2(tff(s[nj][2] - h2), tff(s[nj][3] - h3));
            }
        }
        __syncwarp();

        // O += Phi @ V + Plo @ V
        const unsigned* PuH = (const unsigned*)Phi;
        const unsigned* PuL = (const unsigned*)Plo;
        #pragma unroll
        for (int k8 = 0; k8 < 8; k8++) {
            unsigned pfh[4], pfl[4];
            int r = warp * 16 + (lane >> 2);
            int c = k8 * 8 + (lane & 3);
            pfh[0] = PuH[r * FP + c];
            pfh[1] = PuH[(r + 8) * FP + c];
            pfh[2] = PuH[r * FP + c + 4];
            pfh[3] = PuH[(r + 8) * FP + c + 4];
            pfl[0] = PuL[r * FP + c];
            pfl[1] = PuL[(r + 8) * FP + c];
            pfl[2] = PuL[r * FP + c + 4];
            pfl[3] = PuL[(r + 8) * FP + c + 4];
            #pragma unroll
            for (int nj = 0; nj < 8; nj++) {
                unsigned b0 = Vu[(k8 * 8 + (lane & 3)) * FP + nj * 8 + (lane >> 2)];
                unsigned b1 = Vu[(k8 * 8 + (lane & 3) + 4) * FP + nj * 8 + (lane >> 2)];
                mma_tf32(o[nj], pfh, b0, b1);
                mma_tf32(o[nj], pfl, b0, b1);
            }
        }

        // protect K/V stages: next iteration's prefetch overwrites the stage
        // we just read. All warps must finish PV before that.
        __syncthreads();
    }

    float inv0 = 1.f / l0, inv1 = 1.f / l1;
    size_t row0 = (size_t)b * TT + qt * 128 + warp * 16 + (lane >> 2);
    #pragma unroll
    for (int nj = 0; nj < 8; nj++) {
        int col = h * EE + nj * 8 + 2 * (lane & 3);
        *(float2*)&attout[row0 * DD + col] =
            make_float2(tff(o[nj][0] * inv0), tff(o[nj][1] * inv0));
        *(float2*)&attout[(row0 + 8) * DD + col] =
            make_float2(tff(o[nj][2] * inv1), tff(o[nj][3] * inv1));
    }
}

// ---------------- launch ----------------
extern "C" void kernel_launch(void* const* d_in, const int* in_sizes, int n_in,
                              void* d_out, int out_size) {
    (void)in_sizes; (void)n_in; (void)out_size;
    const float* x      = (const float*)d_in[0];
    const float* wq     = (const float*)d_in[1];
    const float* wk     = (const float*)d_in[2];
    const float* wv     = (const float*)d_in[3];
    const float* w_proj = (const float*)d_in[4];
    const float* b_proj = (const float*)d_in[5];
    const float* w1     = (const float*)d_in[6];
    const float* b1     = (const float*)d_in[7];
    const float* w2     = (const float*)d_in[8];
    const float* b2     = (const float*)d_in[9];
    const float* g1     = (const float*)d_in[10];
    const float* be1    = (const float*)d_in[11];
    const float* g2     = (const float*)d_in[12];
    const float* be2    = (const float*)d_in[13];
    float* out = (float*)d_out;

    float *p_xn, *p_xnr, *p_qkv, *p_wcat, *p_att, *p_x2, *p_xn2, *p_xn2r, *p_h;
    float *p_wpr, *p_w1r, *p_w2r;
    cudaGetSymbolAddress((void**)&p_xn,   g_xn);
    cudaGetSymbolAddress((void**)&p_xnr,  g_xnr);
    cudaGetSymbolAddress((void**)&p_qkv,  g_qkv);
    cudaGetSymbolAddress((void**)&p_wcat, g_wcat);
    cudaGetSymbolAddress((void**)&p_att,  g_att);
    cudaGetSymbolAddress((void**)&p_x2,   g_x2);
    cudaGetSymbolAddress((void**)&p_xn2,  g_xn2);
    cudaGetSymbolAddress((void**)&p_xn2r, g_xn2r);
    cudaGetSymbolAddress((void**)&p_h,    g_h);
    cudaGetSymbolAddress((void**)&p_wpr,  g_wpr);
    cudaGetSymbolAddress((void**)&p_w1r,  g_w1r);
    cudaGetSymbolAddress((void**)&p_w2r,  g_w2r);

    const int FLASH_SMEM = (4 * KTILE_F + 2 * 128 * FP) * sizeof(float);
    cudaFuncSetAttribute(flash_kernel, cudaFuncAttributeMaxDynamicSharedMemorySize, FLASH_SMEM);

    // 0. weight preprocessing (tf32 rounding)
    concat_w<<<(DD * 3 * DD / 4) / 256, 256>>>(wq, wk, wv, p_wcat);
    round_w<<<(DD * DD / 4) / 256, 256>>>(w_proj, p_wpr);
    round_w<<<(DD * FF / 4) / 256, 256>>>(w1, p_w1r);
    round_w<<<(FF * DD / 4) / 256, 256>>>(w2, p_w2r);

    // 1. LN1 (exact + rounded)
    ln_kernel<<<BT, 256>>>(x, g1, be1, p_xn, p_xnr);

    // 2. fused QKV projection (rounded output)
    tgemm<<<dim3(3 * DD / 128, BT / 128), 256>>>(p_xnr, p_wcat, p_qkv,
                                                 BT, 3 * DD, DD, nullptr, nullptr, 0, 1);

    // 3. causal attention (rounded output)
    flash_kernel<<<dim3(TT / 128, BB * HH), 256, FLASH_SMEM>>>(p_qkv, p_att);

    // 4. output projection + bias + residual(xn exact)
    tgemm<<<dim3(DD / 128, BT / 128), 256>>>(p_att, p_wpr, p_x2,
                                             BT, DD, DD, b_proj, p_xn, 0, 0);

    // 5. LN2 (exact + rounded)
    ln_kernel<<<BT, 256>>>(p_x2, g2, be2, p_xn2, p_xn2r);

    // 6. FFN1 (ReLU, rounded output)
    tgemm<<<dim3(FF / 128, BT / 128), 256>>>(p_xn2r, p_w1r, p_h,
                                             BT, FF, DD, b1, nullptr, 1, 1);

    // 7. FFN2 + bias + residual(xn2 exact) -> out
    tgemm<<<dim3(DD / 128, BT / 128), 256>>>(p_h, p_w2r, out,
                                             BT, DD, FF, b2, p_xn2, 0, 0);
}

// round 5
// speedup vs baseline: 3.8921x; 1.3648x over previous
#include <cuda_runtime.h>
#include <cuda_fp16.h>
#include <math.h>
#include <stdint.h>

#define BB   8
#define TT   1024
#define DD   1024
#define HH   16
#define EE   64
#define FF   4096
#define BT   (BB*TT)   // 8192

// ---------------- scratch (device globals; no allocs allowed) ----------------
__device__ float  g_xn  [BT*DD];     // LN1 exact (residual for proj)
__device__ float  g_x2  [BT*DD];     // after attn residual (exact)
__device__ float  g_xn2 [BT*DD];     // LN2 exact (residual for FFN2)
__device__ __half g_xnh [BT*DD];     // LN1 f16 (GEMM A)
__device__ __half g_qkvh[BT*3*DD];   // fused QKV f16 [BT][3072]
__device__ __half g_atth[BT*DD];     // attention out f16
__device__ __half g_xn2h[BT*DD];     // LN2 f16
__device__ __half g_hh  [BT*FF];     // FFN hidden f16
__device__ __half g_wqkvt[3*DD*DD];  // [3072][1024] K-major
__device__ __half g_wpt [DD*DD];     // w_proj^T [1024][1024]
__device__ __half g_w1t [FF*DD];     // w1^T [4096][1024]
__device__ __half g_w2t [DD*FF];     // w2^T [1024][4096]

// ---------------- asm helpers ----------------
__device__ __forceinline__ void mma_f16(float* d, const unsigned* a, unsigned b0, unsigned b1) {
    asm volatile(
        "mma.sync.aligned.m16n8k16.row.col.f32.f16.f16.f32 "
        "{%0,%1,%2,%3}, {%4,%5,%6,%7}, {%8,%9}, {%0,%1,%2,%3};\n"
        : "+f"(d[0]), "+f"(d[1]), "+f"(d[2]), "+f"(d[3])
        : "r"(a[0]), "r"(a[1]), "r"(a[2]), "r"(a[3]), "r"(b0), "r"(b1));
}
#define LDSM4(r0,r1,r2,r3,addr) \
    asm volatile("ldmatrix.sync.aligned.m8n8.x4.shared.b16 {%0,%1,%2,%3}, [%4];" \
        : "=r"(r0), "=r"(r1), "=r"(r2), "=r"(r3) : "r"(addr))
#define LDSM4T(r0,r1,r2,r3,addr) \
    asm volatile("ldmatrix.sync.aligned.m8n8.x4.trans.shared.b16 {%0,%1,%2,%3}, [%4];" \
        : "=r"(r0), "=r"(r1), "=r"(r2), "=r"(r3) : "r"(addr))
#define CP16(sm, gm) asm volatile("cp.async.ca.shared.global [%0], [%1], 16;\n" :: "r"(sm), "l"(gm))

__device__ __forceinline__ unsigned h2u(__half2 h) { return *reinterpret_cast<unsigned*>(&h); }

// ---------------- weight prep: transpose + cvt to f16 ----------------
// out[n][k] (f16) = in[k][n] (f32); grid (N/32, K/32), block (32,8)
__global__ void transpose_cvt(const float* __restrict__ in, __half* __restrict__ out,
                              int K, int N) {
    __shared__ float tile[32][33];
    int n0 = blockIdx.x * 32, k0 = blockIdx.y * 32;
    int tx = threadIdx.x, ty = threadIdx.y;
    #pragma unroll
    for (int i = 0; i < 32; i += 8)
        tile[ty + i][tx] = in[(size_t)(k0 + ty + i) * N + n0 + tx];
    __syncthreads();
    #pragma unroll
    for (int i = 0; i < 32; i += 8)
        out[(size_t)(n0 + ty + i) * K + k0 + tx] = __float2half(tile[tx][ty + i]);
}

// wqkvt[s*1024 + h*64 + e][k] = w_s[h][k][e]; grid (2, 32, 48), block (32,8)
__global__ void qkv_w_prep(const float* __restrict__ wq, const float* __restrict__ wk,
                           const float* __restrict__ wv, __half* __restrict__ wt) {
    __shared__ float tile[32][33];
    int slot = blockIdx.z, s = slot >> 4, h = slot & 15;
    const float* w = ((s == 0) ? wq : (s == 1) ? wk : wv) + (size_t)h * DD * EE;
    __half* o = wt + (size_t)(s * DD + h * EE) * DD;
    int e0 = blockIdx.x * 32, k0 = blockIdx.y * 32;
    int tx = threadIdx.x, ty = threadIdx.y;
    #pragma unroll
    for (int i = 0; i < 32; i += 8)
        tile[ty + i][tx] = w[(size_t)(k0 + ty + i) * EE + e0 + tx];
    __syncthreads();
    #pragma unroll
    for (int i = 0; i < 32; i += 8)
        o[(size_t)(e0 + ty + i) * DD + k0 + tx] = __float2half(tile[tx][ty + i]);
}

// ---------------- LayerNorm: f32 exact + f16 outputs ----------------
__global__ void ln_kernel(const float* __restrict__ x, const float* __restrict__ g,
                          const float* __restrict__ b, float* __restrict__ y,
                          __half* __restrict__ yh) {
    int row = blockIdx.x;
    int tid = threadIdx.x;
    const float4* xr = (const float4*)(x + (size_t)row * DD);
    float4 v = xr[tid];
    float s  = v.x + v.y + v.z + v.w;
    float sq = v.x*v.x + v.y*v.y + v.z*v.z + v.w*v.w;
    #pragma unroll
    for (int m = 16; m >= 1; m >>= 1) {
        s  += __shfl_xor_sync(0xffffffffu, s,  m);
        sq += __shfl_xor_sync(0xffffffffu, sq, m);
    }
    __shared__ float ss[8], ssq[8];
    int wid = tid >> 5, lane = tid & 31;
    if (lane == 0) { ss[wid] = s; ssq[wid] = sq; }
    __syncthreads();
    s = 0.f; sq = 0.f;
    #pragma unroll
    for (int i = 0; i < 8; i++) { s += ss[i]; sq += ssq[i]; }
    float mu   = s * (1.0f / DD);
    float var  = sq * (1.0f / DD) - mu * mu;
    float rstd = rsqrtf(var + 1e-5f);
    float4 gg = ((const float4*)g)[tid];
    float4 bv = ((const float4*)b)[tid];
    float4 o;
    o.x = (v.x - mu) * rstd * gg.x + bv.x;
    o.y = (v.y - mu) * rstd * gg.y + bv.y;
    o.z = (v.z - mu) * rstd * gg.z + bv.z;
    o.w = (v.w - mu) * rstd * gg.w + bv.w;
    ((float4*)(y + (size_t)row * DD))[tid] = o;
    __half2* yh2 = (__half2*)(yh + (size_t)row * DD);
    yh2[tid * 2]     = __floats2half2_rn(o.x, o.y);
    yh2[tid * 2 + 1] = __floats2half2_rn(o.z, o.w);
}

// ---------------- f16 tensor-core GEMM ----------------
// C = A[M,K] @ Bt[N,K]^T, 128x128 CTA tile, 8 warps (32x64), KB=32, 3-stage cp.async
#define KB  32
#define APH 40                 // smem pitch (halves); 20 words -> LDSM conflict-free
#define AST (128*APH)          // halves per stage per matrix

__global__ __launch_bounds__(256, 2) void hgemm(const __half* __restrict__ A,
        const __half* __restrict__ Bt, float* __restrict__ Cf,
        __half* __restrict__ Ch, int M, int N, int K,
        const float* __restrict__ bias, const float* __restrict__ resid, int relu) {
    extern __shared__ __half sh[];
    __half* As = sh;
    __half* Bs = sh + 3 * AST;

    int tid = threadIdx.x, warp = tid >> 5, lane = tid & 31;
    int wm = warp >> 1, wn = warp & 1;
    int m0 = wm * 32, n0 = wn * 64;
    int rowBase = blockIdx.y * 128, colBase = blockIdx.x * 128;

    int lr = tid >> 1, lc = (tid & 1) * 16;
    const __half* Ag = A  + (size_t)(rowBase + lr) * K + lc;
    const __half* Bg = Bt + (size_t)(colBase + lr) * K + lc;
    uint32_t sA = (uint32_t)__cvta_generic_to_shared(As);
    uint32_t sB = (uint32_t)__cvta_generic_to_shared(Bs);
    uint32_t cpA = sA + (lr * APH + lc) * 2;
    uint32_t cpB = sB + (lr * APH + lc) * 2;

    float acc[2][8][4];
    #pragma unroll
    for (int mi = 0; mi < 2; mi++)
        #pragma unroll
        for (int nj = 0; nj < 8; nj++)
            #pragma unroll
            for (int t = 0; t < 4; t++) acc[mi][nj][t] = 0.f;

    int nk = K / KB;

    #pragma unroll
    for (int s = 0; s < 2; s++) {
        CP16(cpA + s * AST * 2,      Ag + s * KB);
        CP16(cpA + s * AST * 2 + 16, Ag + s * KB + 8);
        CP16(cpB + s * AST * 2,      Bg + s * KB);
        CP16(cpB + s * AST * 2 + 16, Bg + s * KB + 8);
        asm volatile("cp.async.commit_group;\n");
    }

    // per-thread fragment base offsets (bytes)
    uint32_t aF = ((m0 + (lane & 15)) * APH + (lane >> 4) * 8) * 2;
    uint32_t bF = ((n0 + (lane & 7) + ((lane >> 4) & 1) * 8) * APH + ((lane >> 3) & 1) * 8) * 2;

    for (int i = 0; i < nk; i++) {
        int ps = i + 2;
        if (ps < nk) {
            int st = ps % 3;
            CP16(cpA + st * AST * 2,      Ag + ps * KB);
            CP16(cpA + st * AST * 2 + 16, Ag + ps * KB + 8);
            CP16(cpB + st * AST * 2,      Bg + ps * KB);
            CP16(cpB + st * AST * 2 + 16, Bg + ps * KB + 8);
        }
        asm volatile("cp.async.commit_group;\n");
        asm volatile("cp.async.wait_group 2;\n");
        __syncthreads();

        int st = i % 3;
        uint32_t aBase = sA + st * AST * 2 + aF;
        uint32_t bBase = sB + st * AST * 2 + bF;
        #pragma unroll
        for (int kk = 0; kk < 2; kk++) {
            unsigned af[2][4];
            LDSM4(af[0][0], af[0][1], af[0][2], af[0][3], aBase + kk * 32);
            LDSM4(af[1][0], af[1][1], af[1][2], af[1][3], aBase + kk * 32 + 16 * APH * 2);
            unsigned bf[8][2];
            #pragma unroll
            for (int j2 = 0; j2 < 4; j2++) {
                unsigned r0, r1, r2, r3;
                LDSM4(r0, r1, r2, r3, bBase + kk * 32 + j2 * (16 * APH * 2));
                bf[2*j2][0] = r0; bf[2*j2][1] = r1;
                bf[2*j2+1][0] = r2; bf[2*j2+1][1] = r3;
            }
            #pragma unroll
            for (int mi = 0; mi < 2; mi++)
                #pragma unroll
                for (int nj = 0; nj < 8; nj++)
                    mma_f16(acc[mi][nj], af[mi], bf[nj][0], bf[nj][1]);
        }
        __syncthreads();
    }

    #pragma unroll
    for (int mi = 0; mi < 2; mi++) {
        int r = rowBase + m0 + mi * 16 + (lane >> 2);
        #pragma unroll
        for (int nj = 0; nj < 8; nj++) {
            int c = colBase + n0 + nj * 8 + 2 * (lane & 3);
            float v0 = acc[mi][nj][0], v1 = acc[mi][nj][1];
            float v2 = acc[mi][nj][2], v3 = acc[mi][nj][3];
            if (bias)  { v0 += bias[c]; v1 += bias[c+1]; v2 += bias[c]; v3 += bias[c+1]; }
            if (relu)  { v0 = fmaxf(v0, 0.f); v1 = fmaxf(v1, 0.f);
                         v2 = fmaxf(v2, 0.f); v3 = fmaxf(v3, 0.f); }
            if (resid) {
                const float* rr0 = resid + (size_t)r * N + c;
                const float* rr1 = resid + (size_t)(r + 8) * N + c;
                v0 += rr0[0]; v1 += rr0[1]; v2 += rr1[0]; v3 += rr1[1];
            }
            if (Cf) {
                *(float2*)&Cf[(size_t)r * N + c]       = make_float2(v0, v1);
                *(float2*)&Cf[(size_t)(r + 8) * N + c] = make_float2(v2, v3);
            }
            if (Ch) {
                *(__half2*)&Ch[(size_t)r * N + c]       = __floats2half2_rn(v0, v1);
                *(__half2*)&Ch[(size_t)(r + 8) * N + c] = __floats2half2_rn(v2, v3);
            }
        }
    }
}

// ---------------- f16 tensor-core flash attention ----------------
// grid (T/128, B*H), 256 threads, K/V tiles 64 double-buffered, P in registers
#define QP 72    // pitch (halves); 36 words -> LDSM conflict-free
__global__ __launch_bounds__(256) void flash_h(const __half* __restrict__ qkv,
                                               __half* __restrict__ attout) {
    extern __shared__ __half fsh[];
    __half* Qs = fsh;                    // 128 x QP
    __half* Ks = fsh + 128 * QP;         // 2 x 64 x QP
    __half* Vs = Ks + 2 * 64 * QP;       // 2 x 64 x QP

    int tid = threadIdx.x, warp = tid >> 5, lane = tid & 31;
    int qt = blockIdx.x;
    int bh = blockIdx.y;
    int b = bh >> 4, h = bh & 15;
    const __half* Qg = qkv + (size_t)b * TT * (3 * DD) + h * EE;
    const __half* Kg = Qg + DD;
    const __half* Vg = Qg + 2 * DD;

    uint32_t sQ = (uint32_t)__cvta_generic_to_shared(Qs);
    uint32_t sK = (uint32_t)__cvta_generic_to_shared(Ks);
    uint32_t sV = (uint32_t)__cvta_generic_to_shared(Vs);

    // Q tile: 128 rows x 8 chunks
    for (int i = tid; i < 1024; i += 256) {
        int r = i >> 3, c = (i & 7) * 8;
        CP16(sQ + (r * QP + c) * 2, Qg + (size_t)(qt * 128 + r) * (3 * DD) + c);
    }
    asm volatile("cp.async.commit_group;\n");
    // prefetch KV tile 0
    for (int i = tid; i < 512; i += 256) {
        int r = i >> 3, c = (i & 7) * 8;
        CP16(sK + (r * QP + c) * 2, Kg + (size_t)r * (3 * DD) + c);
        CP16(sV + (r * QP + c) * 2, Vg + (size_t)r * (3 * DD) + c);
    }
    asm volatile("cp.async.commit_group;\n");
    asm volatile("cp.async.wait_group 1;\n");   // Q done
    __syncthreads();

    unsigned qf[4][4];
    {
        uint32_t qb = sQ + (((warp * 16 + (lane & 15)) * QP + (lane >> 4) * 8)) * 2;
        #pragma unroll
        for (int kk = 0; kk < 4; kk++)
            LDSM4(qf[kk][0], qf[kk][1], qf[kk][2], qf[kk][3], qb + kk * 32);
    }

    float m0r = -1e30f, m1r = -1e30f, l0 = 0.f, l1 = 0.f;
    float o[8][4];
    #pragma unroll
    for (int nj = 0; nj < 8; nj++)
        #pragma unroll
        for (int t = 0; t < 4; t++) o[nj][t] = 0.f;

    int grow0 = qt * 128 + warp * 16 + (lane >> 2);
    const float scale = 0.125f;
    int nkt = 2 * qt + 2;

    uint32_t kF = (((lane & 7) + ((lane >> 4) & 1) * 8) * QP + ((lane >> 3) & 1) * 8) * 2;
    uint32_t vF = ((((lane & 7) + ((lane >> 3) & 1) * 8)) * QP + (lane >> 4) * 8) * 2;

    for (int kt = 0; kt < nkt; kt++) {
        if (kt + 1 < nkt) {
            int st = (kt + 1) & 1;
            for (int i = tid; i < 512; i += 256) {
                int r = i >> 3, c = (i & 7) * 8;
                CP16(sK + (st * 64 * QP + r * QP + c) * 2,
                     Kg + (size_t)((kt + 1) * 64 + r) * (3 * DD) + c);
                CP16(sV + (st * 64 * QP + r * QP + c) * 2,
                     Vg + (size_t)((kt + 1) * 64 + r) * (3 * DD) + c);
            }
            asm volatile("cp.async.commit_group;\n");
            asm volatile("cp.async.wait_group 1;\n");
        } else {
            asm volatile("cp.async.wait_group 0;\n");
        }
        __syncthreads();

        uint32_t kBase = sK + (kt & 1) * 64 * QP * 2 + kF;
        uint32_t vBase = sV + (kt & 1) * 64 * QP * 2 + vF;

        // S = Q @ K^T
        float s[8][4];
        #pragma unroll
        for (int nj = 0; nj < 8; nj++)
            #pragma unroll
            for (int t = 0; t < 4; t++) s[nj][t] = 0.f;

        #pragma unroll
        for (int kk = 0; kk < 4; kk++) {
            unsigned bf[8][2];
            #pragma unroll
            for (int j2 = 0; j2 < 4; j2++) {
                unsigned r0, r1, r2, r3;
                LDSM4(r0, r1, r2, r3, kBase + kk * 32 + j2 * (16 * QP * 2));
                bf[2*j2][0] = r0; bf[2*j2][1] = r1;
                bf[2*j2+1][0] = r2; bf[2*j2+1][1] = r3;
            }
            #pragma unroll
            for (int nj = 0; nj < 8; nj++)
                mma_f16(s[nj], qf[kk], bf[nj][0], bf[nj][1]);
        }

        // scale + causal mask
        bool diag = (kt >= 2 * qt);
        #pragma unroll
        for (int nj = 0; nj < 8; nj++) {
            s[nj][0] *= scale; s[nj][1] *= scale;
            s[nj][2] *= scale; s[nj][3] *= scale;
            if (diag) {
                int gc = kt * 64 + nj * 8 + 2 * (lane & 3);
                if (gc     > grow0)     s[nj][0] = -1e30f;
                if (gc + 1 > grow0)     s[nj][1] = -1e30f;
                if (gc     > grow0 + 8) s[nj][2] = -1e30f;
                if (gc + 1 > grow0 + 8) s[nj][3] = -1e30f;
            }
        }

        // online softmax
        float mx0 = -1e30f, mx1 = -1e30f;
        #pragma unroll
        for (int nj = 0; nj < 8; nj++) {
            mx0 = fmaxf(mx0, fmaxf(s[nj][0], s[nj][1]));
            mx1 = fmaxf(mx1, fmaxf(s[nj][2], s[nj][3]));
        }
        mx0 = fmaxf(mx0, __shfl_xor_sync(0xffffffffu, mx0, 1));
        mx0 = fmaxf(mx0, __shfl_xor_sync(0xffffffffu, mx0, 2));
        mx1 = fmaxf(mx1, __shfl_xor_sync(0xffffffffu, mx1, 1));
        mx1 = fmaxf(mx1, __shfl_xor_sync(0xffffffffu, mx1, 2));
        float mn0 = fmaxf(m0r, mx0), mn1 = fmaxf(m1r, mx1);
        float f0 = __expf(m0r - mn0), f1 = __expf(m1r - mn1);
        m0r = mn0; m1r = mn1;
        float rs0 = 0.f, rs1 = 0.f;
        #pragma unroll
        for (int nj = 0; nj < 8; nj++) {
            s[nj][0] = __expf(s[nj][0] - mn0); rs0 += s[nj][0];
            s[nj][1] = __expf(s[nj][1] - mn0); rs0 += s[nj][1];
            s[nj][2] = __expf(s[nj][2] - mn1); rs1 += s[nj][2];
            s[nj][3] = __expf(s[nj][3] - mn1); rs1 += s[nj][3];
        }
        rs0 += __shfl_xor_sync(0xffffffffu, rs0, 1);
        rs0 += __shfl_xor_sync(0xffffffffu, rs0, 2);
        rs1 += __shfl_xor_sync(0xffffffffu, rs1, 1);
        rs1 += __shfl_xor_sync(0xffffffffu, rs1, 2);
        l0 = l0 * f0 + rs0;
        l1 = l1 * f1 + rs1;
        #pragma unroll
        for (int nj = 0; nj < 8; nj++) {
            o[nj][0] *= f0; o[nj][1] *= f0;
            o[nj][2] *= f1; o[nj][3] *= f1;
        }

        // O += P @ V  (P hi/lo in registers, V via ldmatrix.trans)
        #pragma unroll
        for (int kb = 0; kb < 4; kb++) {
            unsigned ph[4], pl[4];
            #pragma unroll
            for (int q = 0; q < 2; q++) {          // q=0: block 2kb rows r/r+8, q=1: block 2kb+1
                int blk = 2 * kb + q;
                __half2 h0 = __floats2half2_rn(s[blk][0], s[blk][1]);
                __half2 h1 = __floats2half2_rn(s[blk][2], s[blk][3]);
                float2 f0v = __half22float2(h0);
                float2 f1v = __half22float2(h1);
                __half2 e0 = __floats2half2_rn(s[blk][0] - f0v.x, s[blk][1] - f0v.y);
                __half2 e1 = __floats2half2_rn(s[blk][2] - f1v.x, s[blk][3] - f1v.y);
                ph[2*q]   = h2u(h0); ph[2*q+1] = h2u(h1);
                pl[2*q]   = h2u(e0); pl[2*q+1] = h2u(e1);
            }
            #pragma unroll
            for (int j2 = 0; j2 < 4; j2++) {
                unsigned b0, b1, b2, b3;
                LDSM4T(b0, b1, b2, b3, vBase + kb * (16 * QP * 2) + j2 * 32);
                mma_f16(o[2*j2],   ph, b0, b1);
                mma_f16(o[2*j2],   pl, b0, b1);
                mma_f16(o[2*j2+1], ph, b2, b3);
                mma_f16(o[2*j2+1], pl, b2, b3);
            }
        }
        __syncthreads();   // protect K/V stages from next prefetch
    }

    float inv0 = 1.f / l0, inv1 = 1.f / l1;
    size_t row0 = (size_t)b * TT + qt * 128 + warp * 16 + (lane >> 2);
    #pragma unroll
    for (int nj = 0; nj < 8; nj++) {
        int col = h * EE + nj * 8 + 2 * (lane & 3);
        *(__half2*)&attout[row0 * DD + col] =
            __floats2half2_rn(o[nj][0] * inv0, o[nj][1] * inv0);
        *(__half2*)&attout[(row0 + 8) * DD + col] =
            __floats2half2_rn(o[nj][2] * inv1, o[nj][3] * inv1);
    }
}

// ---------------- launch ----------------
extern "C" void kernel_launch(void* const* d_in, const int* in_sizes, int n_in,
                              void* d_out, int out_size) {
    (void)in_sizes; (void)n_in; (void)out_size;
    const float* x      = (const float*)d_in[0];
    const float* wq     = (const float*)d_in[1];
    const float* wk     = (const float*)d_in[2];
    const float* wv     = (const float*)d_in[3];
    const float* w_proj = (const float*)d_in[4];
    const float* b_proj = (const float*)d_in[5];
    const float* w1     = (const float*)d_in[6];
    const float* b1     = (const float*)d_in[7];
    const float* w2     = (const float*)d_in[8];
    const float* b2     = (const float*)d_in[9];
    const float* g1     = (const float*)d_in[10];
    const float* be1    = (const float*)d_in[11];
    const float* g2     = (const float*)d_in[12];
    const float* be2    = (const float*)d_in[13];
    float* out = (float*)d_out;

    float *p_xn, *p_x2, *p_xn2;
    __half *p_xnh, *p_qkvh, *p_atth, *p_xn2h, *p_hh, *p_wqkvt, *p_wpt, *p_w1t, *p_w2t;
    cudaGetSymbolAddress((void**)&p_xn,    g_xn);
    cudaGetSymbolAddress((void**)&p_x2,    g_x2);
    cudaGetSymbolAddress((void**)&p_xn2,   g_xn2);
    cudaGetSymbolAddress((void**)&p_xnh,   g_xnh);
    cudaGetSymbolAddress((void**)&p_qkvh,  g_qkvh);
    cudaGetSymbolAddress((void**)&p_atth,  g_atth);
    cudaGetSymbolAddress((void**)&p_xn2h,  g_xn2h);
    cudaGetSymbolAddress((void**)&p_hh,    g_hh);
    cudaGetSymbolAddress((void**)&p_wqkvt, g_wqkvt);
    cudaGetSymbolAddress((void**)&p_wpt,   g_wpt);
    cudaGetSymbolAddress((void**)&p_w1t,   g_w1t);
    cudaGetSymbolAddress((void**)&p_w2t,   g_w2t);

    const int GEMM_SMEM  = 6 * AST * 2;                 // 61440 B
    const int FLASH_SMEM = (128 + 4 * 64) * QP * 2;     // 55296 B
    cudaFuncSetAttribute(hgemm,   cudaFuncAttributeMaxDynamicSharedMemorySize, GEMM_SMEM);
    cudaFuncSetAttribute(flash_h, cudaFuncAttributeMaxDynamicSharedMemorySize, FLASH_SMEM);

    // 0. weight prep (f16 + transpose)
    qkv_w_prep<<<dim3(2, 32, 48), dim3(32, 8)>>>(wq, wk, wv, p_wqkvt);
    transpose_cvt<<<dim3(32, 32),  dim3(32, 8)>>>(w_proj, p_wpt, DD, DD);
    transpose_cvt<<<dim3(128, 32), dim3(32, 8)>>>(w1, p_w1t, DD, FF);
    transpose_cvt<<<dim3(32, 128), dim3(32, 8)>>>(w2, p_w2t, FF, DD);

    // 1. LN1
    ln_kernel<<<BT, 256>>>(x, g1, be1, p_xn, p_xnh);

    // 2. fused QKV projection -> f16
    hgemm<<<dim3(24, 64), 256, GEMM_SMEM>>>(p_xnh, p_wqkvt, nullptr, p_qkvh,
                                            BT, 3 * DD, DD, nullptr, nullptr, 0);

    // 3. causal attention -> f16
    flash_h<<<dim3(TT / 128, BB * HH), 256, FLASH_SMEM>>>(p_qkvh, p_atth);

    // 4. output projection + bias + residual(xn exact) -> f32
    hgemm<<<dim3(8, 64), 256, GEMM_SMEM>>>(p_atth, p_wpt, p_x2, nullptr,
                                           BT, DD, DD, b_proj, p_xn, 0);

    // 5. LN2
    ln_kernel<<<BT, 256>>>(p_x2, g2, be2, p_xn2, p_xn2h);

    // 6. FFN1 (bias + ReLU) -> f16
    hgemm<<<dim3(32, 64), 256, GEMM_SMEM>>>(p_xn2h, p_w1t, nullptr, p_hh,
                                            BT, FF, DD, b1, nullptr, 1);

    // 7. FFN2 + bias + residual(xn2 exact) -> out f32
    hgemm<<<dim3(8, 64), 256, GEMM_SMEM>>>(p_hh, p_w2t, out, nullptr,
                                           BT, DD, FF, b2, p_xn2, 0);
}

// round 7
// speedup vs baseline: 4.9933x; 1.2829x over previous
#include <cuda_runtime.h>
#include <cuda_fp16.h>
#include <math.h>
#include <stdint.h>

#define BB   8
#define TT   1024
#define DD   1024
#define HH   16
#define EE   64
#define FF   4096
#define BT   (BB*TT)   // 8192

// ---------------- scratch (device globals; no allocs allowed) ----------------
__device__ float  g_xn  [BT*DD];     // LN1 exact (residual for proj)
__device__ float  g_x2  [BT*DD];     // after attn residual (exact)
__device__ float  g_xn2 [BT*DD];     // LN2 exact (residual for FFN2)
__device__ __half g_xnh [BT*DD];     // LN1 f16 (GEMM A)
__device__ __half g_qkvh[BT*3*DD];   // fused QKV f16 [BT][3072]
__device__ __half g_atth[BT*DD];     // attention out f16
__device__ __half g_xn2h[BT*DD];     // LN2 f16
__device__ __half g_hh  [BT*FF];     // FFN hidden f16
__device__ __half g_wqkvt[3*DD*DD];  // [3072][1024] K-major
__device__ __half g_wpt [DD*DD];     // w_proj^T [1024][1024]
__device__ __half g_w1t [FF*DD];     // w1^T [4096][1024]
__device__ __half g_w2t [DD*FF];     // w2^T [1024][4096]

// ---------------- asm helpers ----------------
__device__ __forceinline__ void mma_f16(float* d, const unsigned* a, unsigned b0, unsigned b1) {
    asm volatile(
        "mma.sync.aligned.m16n8k16.row.col.f32.f16.f16.f32 "
        "{%0,%1,%2,%3}, {%4,%5,%6,%7}, {%8,%9}, {%0,%1,%2,%3};\n"
        : "+f"(d[0]), "+f"(d[1]), "+f"(d[2]), "+f"(d[3])
        : "r"(a[0]), "r"(a[1]), "r"(a[2]), "r"(a[3]), "r"(b0), "r"(b1));
}
#define LDSM4(r0,r1,r2,r3,addr) \
    asm volatile("ldmatrix.sync.aligned.m8n8.x4.shared.b16 {%0,%1,%2,%3}, [%4];" \
        : "=r"(r0), "=r"(r1), "=r"(r2), "=r"(r3) : "r"(addr))
#define LDSM4T(r0,r1,r2,r3,addr) \
    asm volatile("ldmatrix.sync.aligned.m8n8.x4.trans.shared.b16 {%0,%1,%2,%3}, [%4];" \
        : "=r"(r0), "=r"(r1), "=r"(r2), "=r"(r3) : "r"(addr))
#define CP16(sm, gm) asm volatile("cp.async.ca.shared.global [%0], [%1], 16;\n" :: "r"(sm), "l"(gm))

__device__ __forceinline__ unsigned h2u(__half2 h) { return *reinterpret_cast<unsigned*>(&h); }

// ---------------- weight prep: transpose + cvt to f16 ----------------
__global__ void transpose_cvt(const float* __restrict__ in, __half* __restrict__ out,
                              int K, int N) {
    __shared__ float tile[32][33];
    int n0 = blockIdx.x * 32, k0 = blockIdx.y * 32;
    int tx = threadIdx.x, ty = threadIdx.y;
    #pragma unroll
    for (int i = 0; i < 32; i += 8)
        tile[ty + i][tx] = in[(size_t)(k0 + ty + i) * N + n0 + tx];
    __syncthreads();
    #pragma unroll
    for (int i = 0; i < 32; i += 8)
        out[(size_t)(n0 + ty + i) * K + k0 + tx] = __float2half(tile[tx][ty + i]);
}

__global__ void qkv_w_prep(const float* __restrict__ wq, const float* __restrict__ wk,
                           const float* __restrict__ wv, __half* __restrict__ wt) {
    __shared__ float tile[32][33];
    int slot = blockIdx.z, s = slot >> 4, h = slot & 15;
    const float* w = ((s == 0) ? wq : (s == 1) ? wk : wv) + (size_t)h * DD * EE;
    __half* o = wt + (size_t)(s * DD + h * EE) * DD;
    int e0 = blockIdx.x * 32, k0 = blockIdx.y * 32;
    int tx = threadIdx.x, ty = threadIdx.y;
    #pragma unroll
    for (int i = 0; i < 32; i += 8)
        tile[ty + i][tx] = w[(size_t)(k0 + ty + i) * EE + e0 + tx];
    __syncthreads();
    #pragma unroll
    for (int i = 0; i < 32; i += 8)
        o[(size_t)(e0 + ty + i) * DD + k0 + tx] = __float2half(tile[tx][ty + i]);
}

// ---------------- LayerNorm: f32 exact + f16 outputs ----------------
__global__ void ln_kernel(const float* __restrict__ x, const float* __restrict__ g,
                          const float* __restrict__ b, float* __restrict__ y,
                          __half* __restrict__ yh) {
    int row = blockIdx.x;
    int tid = threadIdx.x;
    const float4* xr = (const float4*)(x + (size_t)row * DD);
    float4 v = xr[tid];
    float s  = v.x + v.y + v.z + v.w;
    float sq = v.x*v.x + v.y*v.y + v.z*v.z + v.w*v.w;
    #pragma unroll
    for (int m = 16; m >= 1; m >>= 1) {
        s  += __shfl_xor_sync(0xffffffffu, s,  m);
        sq += __shfl_xor_sync(0xffffffffu, sq, m);
    }
    __shared__ float ss[8], ssq[8];
    int wid = tid >> 5, lane = tid & 31;
    if (lane == 0) { ss[wid] = s; ssq[wid] = sq; }
    __syncthreads();
    s = 0.f; sq = 0.f;
    #pragma unroll
    for (int i = 0; i < 8; i++) { s += ss[i]; sq += ssq[i]; }
    float mu   = s * (1.0f / DD);
    float var  = sq * (1.0f / DD) - mu * mu;
    float rstd = rsqrtf(var + 1e-5f);
    float4 gg = ((const float4*)g)[tid];
    float4 bv = ((const float4*)b)[tid];
    float4 o;
    o.x = (v.x - mu) * rstd * gg.x + bv.x;
    o.y = (v.y - mu) * rstd * gg.y + bv.y;
    o.z = (v.z - mu) * rstd * gg.z + bv.z;
    o.w = (v.w - mu) * rstd * gg.w + bv.w;
    ((float4*)(y + (size_t)row * DD))[tid] = o;
    __half2* yh2 = (__half2*)(yh + (size_t)row * DD);
    yh2[tid * 2]     = __floats2half2_rn(o.x, o.y);
    yh2[tid * 2 + 1] = __floats2half2_rn(o.z, o.w);
}

// ---------------- f16 tensor-core GEMM: multistage, KB=64, 3 stages --------
// C = A[M,K] @ Bt[N,K]^T. 128x128 CTA tile, 8 warps (32x64 each).
#define KB2  64
#define PH   72                  // smem pitch (halves); 36 words -> conflict-free
#define STG  (128*PH)            // halves per operand per stage (9216)
#define NSTG 3
#define GEMM_SMEM (NSTG * 2 * STG * 2)   // 110592 B

__global__ __launch_bounds__(256) void hgemm(const __half* __restrict__ A,
        const __half* __restrict__ Bt, float* __restrict__ Cf,
        __half* __restrict__ Ch, int M, int N, int K,
        const float* __restrict__ bias, const float* __restrict__ resid, int relu) {
    extern __shared__ __half sh[];
    __half* As = sh;                  // NSTG stages
    __half* Bs = sh + NSTG * STG;

    int tid = threadIdx.x, warp = tid >> 5, lane = tid & 31;
    int wm = warp >> 1, wn = warp & 1;
    int m0 = wm * 32, n0 = wn * 64;
    int rowBase = blockIdx.y * 128, colBase = blockIdx.x * 128;

    // cp.async mapping: row = tid>>1, cols ((tid&1)*4 + j)*8, j=0..3
    int lr = tid >> 1, lcb = (tid & 1) * 32;
    const __half* Ag = A  + (size_t)(rowBase + lr) * K + lcb;
    const __half* Bg = Bt + (size_t)(colBase + lr) * K + lcb;
    uint32_t sA = (uint32_t)__cvta_generic_to_shared(As);
    uint32_t sB = (uint32_t)__cvta_generic_to_shared(Bs);
    uint32_t cpOff = (lr * PH + lcb) * 2;

    #define HG_LOAD(k0, st) do { \
        uint32_t aS = sA + (st) * STG * 2 + cpOff; \
        uint32_t bS = sB + (st) * STG * 2 + cpOff; \
        const __half* ag = Ag + (k0); \
        const __half* bg = Bg + (k0); \
        _Pragma("unroll") \
        for (int j = 0; j < 4; j++) { \
            CP16(aS + j * 16, ag + j * 8); \
            CP16(bS + j * 16, bg + j * 8); \
        } \
    } while (0)

    float acc[2][8][4];
    #pragma unroll
    for (int mi = 0; mi < 2; mi++)
        #pragma unroll
        for (int nj = 0; nj < 8; nj++)
            #pragma unroll
            for (int t = 0; t < 4; t++) acc[mi][nj][t] = 0.f;

    int nk = K / KB2;

    HG_LOAD(0, 0);
    asm volatile("cp.async.commit_group;\n");
    HG_LOAD(KB2, 1);
    asm volatile("cp.async.commit_group;\n");

    // fragment base offsets (bytes) within a stage
    uint32_t aF = ((m0 + (lane & 15)) * PH + (lane >> 4) * 8) * 2;
    uint32_t bF = ((n0 + (lane & 7) + ((lane >> 4) & 1) * 8) * PH + ((lane >> 3) & 1) * 8) * 2;

    for (int i = 0; i < nk; i++) {
        asm volatile("cp.async.wait_group 1;\n");   // stage i ready
        __syncthreads();                             // all warps done with stage (i-1)

        int ps = i + 2;
        if (ps < nk) HG_LOAD(ps * KB2, ps % NSTG);   // overwrites stage computed at i-1: safe
        asm volatile("cp.async.commit_group;\n");

        int st = i % NSTG;
        uint32_t aBase = sA + st * STG * 2 + aF;
        uint32_t bBase = sB + st * STG * 2 + bF;
        #pragma unroll
        for (int kk = 0; kk < 4; kk++) {             // 4 x k16 slices
            unsigned af[2][4];
            LDSM4(af[0][0], af[0][1], af[0][2], af[0][3], aBase + kk * 32);
            LDSM4(af[1][0], af[1][1], af[1][2], af[1][3], aBase + kk * 32 + 16 * PH * 2);
            unsigned bf[8][2];
            #pragma unroll
            for (int j2 = 0; j2 < 4; j2++) {
                unsigned r0, r1, r2, r3;
                LDSM4(r0, r1, r2, r3, bBase + kk * 32 + j2 * (16 * PH * 2));
                bf[2*j2][0] = r0; bf[2*j2][1] = r1;
                bf[2*j2+1][0] = r2; bf[2*j2+1][1] = r3;
            }
            #pragma unroll
            for (int mi = 0; mi < 2; mi++)
                #pragma unroll
                for (int nj = 0; nj < 8; nj++)
                    mma_f16(acc[mi][nj], af[mi], bf[nj][0], bf[nj][1]);
        }
    }

    #pragma unroll
    for (int mi = 0; mi < 2; mi++) {
        int r = rowBase + m0 + mi * 16 + (lane >> 2);
        #pragma unroll
        for (int nj = 0; nj < 8; nj++) {
            int c = colBase + n0 + nj * 8 + 2 * (lane & 3);
            float v0 = acc[mi][nj][0], v1 = acc[mi][nj][1];
            float v2 = acc[mi][nj][2], v3 = acc[mi][nj][3];
            if (bias)  { v0 += bias[c]; v1 += bias[c+1]; v2 += bias[c]; v3 += bias[c+1]; }
            if (relu)  { v0 = fmaxf(v0, 0.f); v1 = fmaxf(v1, 0.f);
                         v2 = fmaxf(v2, 0.f); v3 = fmaxf(v3, 0.f); }
            if (resid) {
                const float* rr0 = resid + (size_t)r * N + c;
                const float* rr1 = resid + (size_t)(r + 8) * N + c;
                v0 += rr0[0]; v1 += rr0[1]; v2 += rr1[0]; v3 += rr1[1];
            }
            if (Cf) {
                *(float2*)&Cf[(size_t)r * N + c]       = make_float2(v0, v1);
                *(float2*)&Cf[(size_t)(r + 8) * N + c] = make_float2(v2, v3);
            }
            if (Ch) {
                *(__half2*)&Ch[(size_t)r * N + c]       = __floats2half2_rn(v0, v1);
                *(__half2*)&Ch[(size_t)(r + 8) * N + c] = __floats2half2_rn(v2, v3);
            }
        }
    }
}

// ---------------- f16 tensor-core flash attention ----------------
#define QP 72
__global__ __launch_bounds__(256) void flash_h(const __half* __restrict__ qkv,
                                               __half* __restrict__ attout) {
    extern __shared__ __half fsh[];
    __half* Qs = fsh;
    __half* Ks = fsh + 128 * QP;
    __half* Vs = Ks + 2 * 64 * QP;

    int tid = threadIdx.x, warp = tid >> 5, lane = tid & 31;
    int qt = blockIdx.x;
    int bh = blockIdx.y;
    int b = bh >> 4, h = bh & 15;
    const __half* Qg = qkv + (size_t)b * TT * (3 * DD) + h * EE;
    const __half* Kg = Qg + DD;
    const __half* Vg = Qg + 2 * DD;

    uint32_t sQ = (uint32_t)__cvta_generic_to_shared(Qs);
    uint32_t sK = (uint32_t)__cvta_generic_to_shared(Ks);
    uint32_t sV = (uint32_t)__cvta_generic_to_shared(Vs);

    for (int i = tid; i < 1024; i += 256) {
        int r = i >> 3, c = (i & 7) * 8;
        CP16(sQ + (r * QP + c) * 2, Qg + (size_t)(qt * 128 + r) * (3 * DD) + c);
    }
    asm volatile("cp.async.commit_group;\n");
    for (int i = tid; i < 512; i += 256) {
        int r = i >> 3, c = (i & 7) * 8;
        CP16(sK + (r * QP + c) * 2, Kg + (size_t)r * (3 * DD) + c);
        CP16(sV + (r * QP + c) * 2, Vg + (size_t)r * (3 * DD) + c);
    }
    asm volatile("cp.async.commit_group;\n");
    asm volatile("cp.async.wait_group 1;\n");
    __syncthreads();

    unsigned qf[4][4];
    {
        uint32_t qb = sQ + (((warp * 16 + (lane & 15)) * QP + (lane >> 4) * 8)) * 2;
        #pragma unroll
        for (int kk = 0; kk < 4; kk++)
            LDSM4(qf[kk][0], qf[kk][1], qf[kk][2], qf[kk][3], qb + kk * 32);
    }

    float m0r = -1e30f, m1r = -1e30f, l0 = 0.f, l1 = 0.f;
    float o[8][4];
    #pragma unroll
    for (int nj = 0; nj < 8; nj++)
        #pragma unroll
        for (int t = 0; t < 4; t++) o[nj][t] = 0.f;

    int grow0 = qt * 128 + warp * 16 + (lane >> 2);
    const float scale = 0.125f;
    int nkt = 2 * qt + 2;

    uint32_t kF = (((lane & 7) + ((lane >> 4) & 1) * 8) * QP + ((lane >> 3) & 1) * 8) * 2;
    uint32_t vF = ((((lane & 7) + ((lane >> 3) & 1) * 8)) * QP + (lane >> 4) * 8) * 2;

    for (int kt = 0; kt < nkt; kt++) {
        if (kt + 1 < nkt) {
            int st = (kt + 1) & 1;
            for (int i = tid; i < 512; i += 256) {
                int r = i >> 3, c = (i & 7) * 8;
                CP16(sK + (st * 64 * QP + r * QP + c) * 2,
                     Kg + (size_t)((kt + 1) * 64 + r) * (3 * DD) + c);
                CP16(sV + (st * 64 * QP + r * QP + c) * 2,
                     Vg + (size_t)((kt + 1) * 64 + r) * (3 * DD) + c);
            }
            asm volatile("cp.async.commit_group;\n");
            asm volatile("cp.async.wait_group 1;\n");
        } else {
            asm volatile("cp.async.wait_group 0;\n");
        }
        __syncthreads();

        uint32_t kBase = sK + (kt & 1) * 64 * QP * 2 + kF;
        uint32_t vBase = sV + (kt & 1) * 64 * QP * 2 + vF;

        float s[8][4];
        #pragma unroll
        for (int nj = 0; nj < 8; nj++)
            #pragma unroll
            for (int t = 0; t < 4; t++) s[nj][t] = 0.f;

        #pragma unroll
        for (int kk = 0; kk < 4; kk++) {
            unsigned bf[8][2];
            #pragma unroll
            for (int j2 = 0; j2 < 4; j2++) {
                unsigned r0, r1, r2, r3;
                LDSM4(r0, r1, r2, r3, kBase + kk * 32 + j2 * (16 * QP * 2));
                bf[2*j2][0] = r0; bf[2*j2][1] = r1;
                bf[2*j2+1][0] = r2; bf[2*j2+1][1] = r3;
            }
            #pragma unroll
            for (int nj = 0; nj < 8; nj++)
                mma_f16(s[nj], qf[kk], bf[nj][0], bf[nj][1]);
        }

        bool diag = (kt >= 2 * qt);
        #pragma unroll
        for (int nj = 0; nj < 8; nj++) {
            s[nj][0] *= scale; s[nj][1] *= scale;
            s[nj][2] *= scale; s[nj][3] *= scale;
            if (diag) {
                int gc = kt * 64 + nj * 8 + 2 * (lane & 3);
                if (gc     > grow0)     s[nj][0] = -1e30f;
                if (gc + 1 > grow0)     s[nj][1] = -1e30f;
                if (gc     > grow0 + 8) s[nj][2] = -1e30f;
                if (gc + 1 > grow0 + 8) s[nj][3] = -1e30f;
            }
        }

        float mx0 = -1e30f, mx1 = -1e30f;
        #pragma unroll
        for (int nj = 0; nj < 8; nj++) {
            mx0 = fmaxf(mx0, fmaxf(s[nj][0], s[nj][1]));
            mx1 = fmaxf(mx1, fmaxf(s[nj][2], s[nj][3]));
        }
        mx0 = fmaxf(mx0, __shfl_xor_sync(0xffffffffu, mx0, 1));
        mx0 = fmaxf(mx0, __shfl_xor_sync(0xffffffffu, mx0, 2));
        mx1 = fmaxf(mx1, __shfl_xor_sync(0xffffffffu, mx1, 1));
        mx1 = fmaxf(mx1, __shfl_xor_sync(0xffffffffu, mx1, 2));
        float mn0 = fmaxf(m0r, mx0), mn1 = fmaxf(m1r, mx1);
        float f0 = __expf(m0r - mn0), f1 = __expf(m1r - mn1);
        m0r = mn0; m1r = mn1;
        float rs0 = 0.f, rs1 = 0.f;
        #pragma unroll
        for (int nj = 0; nj < 8; nj++) {
            s[nj][0] = __expf(s[nj][0] - mn0); rs0 += s[nj][0];
            s[nj][1] = __expf(s[nj][1] - mn0); rs0 += s[nj][1];
            s[nj][2] = __expf(s[nj][2] - mn1); rs1 += s[nj][2];
            s[nj][3] = __expf(s[nj][3] - mn1); rs1 += s[nj][3];
        }
        rs0 += __shfl_xor_sync(0xffffffffu, rs0, 1);
        rs0 += __shfl_xor_sync(0xffffffffu, rs0, 2);
        rs1 += __shfl_xor_sync(0xffffffffu, rs1, 1);
        rs1 += __shfl_xor_sync(0xffffffffu, rs1, 2);
        l0 = l0 * f0 + rs0;
        l1 = l1 * f1 + rs1;
        #pragma unroll
        for (int nj = 0; nj < 8; nj++) {
            o[nj][0] *= f0; o[nj][1] *= f0;
            o[nj][2] *= f1; o[nj][3] *= f1;
        }

        #pragma unroll
        for (int kb = 0; kb < 4; kb++) {
            unsigned ph[4], pl[4];
            #pragma unroll
            for (int q = 0; q < 2; q++) {
                int blk = 2 * kb + q;
                __half2 h0 = __floats2half2_rn(s[blk][0], s[blk][1]);
                __half2 h1 = __floats2half2_rn(s[blk][2], s[blk][3]);
                float2 f0v = __half22float2(h0);
                float2 f1v = __half22float2(h1);
                __half2 e0 = __floats2half2_rn(s[blk][0] - f0v.x, s[blk][1] - f0v.y);
                __half2 e1 = __floats2half2_rn(s[blk][2] - f1v.x, s[blk][3] - f1v.y);
                ph[2*q]   = h2u(h0); ph[2*q+1] = h2u(h1);
                pl[2*q]   = h2u(e0); pl[2*q+1] = h2u(e1);
            }
            #pragma unroll
            for (int j2 = 0; j2 < 4; j2++) {
                unsigned b0, b1, b2, b3;
                LDSM4T(b0, b1, b2, b3, vBase + kb * (16 * QP * 2) + j2 * 32);
                mma_f16(o[2*j2],   ph, b0, b1);
                mma_f16(o[2*j2],   pl, b0, b1);
                mma_f16(o[2*j2+1], ph, b2, b3);
                mma_f16(o[2*j2+1], pl, b2, b3);
            }
        }
        __syncthreads();
    }

    float inv0 = 1.f / l0, inv1 = 1.f / l1;
    size_t row0 = (size_t)b * TT + qt * 128 + warp * 16 + (lane >> 2);
    #pragma unroll
    for (int nj = 0; nj < 8; nj++) {
        int col = h * EE + nj * 8 + 2 * (lane & 3);
        *(__half2*)&attout[row0 * DD + col] =
            __floats2half2_rn(o[nj][0] * inv0, o[nj][1] * inv0);
        *(__half2*)&attout[(row0 + 8) * DD + col] =
            __floats2half2_rn(o[nj][2] * inv1, o[nj][3] * inv1);
    }
}

// ---------------- launch ----------------
extern "C" void kernel_launch(void* const* d_in, const int* in_sizes, int n_in,
                              void* d_out, int out_size) {
    (void)in_sizes; (void)n_in; (void)out_size;
    const float* x      = (const float*)d_in[0];
    const float* wq     = (const float*)d_in[1];
    const float* wk     = (const float*)d_in[2];
    const float* wv     = (const float*)d_in[3];
    const float* w_proj = (const float*)d_in[4];
    const float* b_proj = (const float*)d_in[5];
    const float* w1     = (const float*)d_in[6];
    const float* b1     = (const float*)d_in[7];
    const float* w2     = (const float*)d_in[8];
    const float* b2     = (const float*)d_in[9];
    const float* g1     = (const float*)d_in[10];
    const float* be1    = (const float*)d_in[11];
    const float* g2     = (const float*)d_in[12];
    const float* be2    = (const float*)d_in[13];
    float* out = (float*)d_out;

    float *p_xn, *p_x2, *p_xn2;
    __half *p_xnh, *p_qkvh, *p_atth, *p_xn2h, *p_hh, *p_wqkvt, *p_wpt, *p_w1t, *p_w2t;
    cudaGetSymbolAddress((void**)&p_xn,    g_xn);
    cudaGetSymbolAddress((void**)&p_x2,    g_x2);
    cudaGetSymbolAddress((void**)&p_xn2,   g_xn2);
    cudaGetSymbolAddress((void**)&p_xnh,   g_xnh);
    cudaGetSymbolAddress((void**)&p_qkvh,  g_qkvh);
    cudaGetSymbolAddress((void**)&p_atth,  g_atth);
    cudaGetSymbolAddress((void**)&p_xn2h,  g_xn2h);
    cudaGetSymbolAddress((void**)&p_hh,    g_hh);
    cudaGetSymbolAddress((void**)&p_wqkvt, g_wqkvt);
    cudaGetSymbolAddress((void**)&p_wpt,   g_wpt);
    cudaGetSymbolAddress((void**)&p_w1t,   g_w1t);
    cudaGetSymbolAddress((void**)&p_w2t,   g_w2t);

    const int FLASH_SMEM = (128 + 4 * 64) * QP * 2;
    cudaFuncSetAttribute(hgemm,   cudaFuncAttributeMaxDynamicSharedMemorySize, GEMM_SMEM);
    cudaFuncSetAttribute(flash_h, cudaFuncAttributeMaxDynamicSharedMemorySize, FLASH_SMEM);

    // 0. weight prep (f16 + transpose)
    qkv_w_prep<<<dim3(2, 32, 48), dim3(32, 8)>>>(wq, wk, wv, p_wqkvt);
    transpose_cvt<<<dim3(32, 32),  dim3(32, 8)>>>(w_proj, p_wpt, DD, DD);
    transpose_cvt<<<dim3(128, 32), dim3(32, 8)>>>(w1, p_w1t, DD, FF);
    transpose_cvt<<<dim3(32, 128), dim3(32, 8)>>>(w2, p_w2t, FF, DD);

    // 1. LN1
    ln_kernel<<<BT, 256>>>(x, g1, be1, p_xn, p_xnh);

    // 2. fused QKV projection -> f16
    hgemm<<<dim3(24, 64), 256, GEMM_SMEM>>>(p_xnh, p_wqkvt, nullptr, p_qkvh,
                                            BT, 3 * DD, DD, nullptr, nullptr, 0);

    // 3. causal attention -> f16
    flash_h<<<dim3(TT / 128, BB * HH), 256, FLASH_SMEM>>>(p_qkvh, p_atth);

    // 4. output projection + bias + residual(xn exact) -> f32
    hgemm<<<dim3(8, 64), 256, GEMM_SMEM>>>(p_atth, p_wpt, p_x2, nullptr,
                                           BT, DD, DD, b_proj, p_xn, 0);

    // 5. LN2
    ln_kernel<<<BT, 256>>>(p_x2, g2, be2, p_xn2, p_xn2h);

    // 6. FFN1 (bias + ReLU) -> f16
    hgemm<<<dim3(32, 64), 256, GEMM_SMEM>>>(p_xn2h, p_w1t, nullptr, p_hh,
                                            BT, FF, DD, b1, nullptr, 1);

    // 7. FFN2 + bias + residual(xn2 exact) -> out f32
    hgemm<<<dim3(8, 64), 256, GEMM_SMEM>>>(p_hh, p_w2t, out, nullptr,
                                           BT, DD, FF, b2, p_xn2, 0);
}

// round 8
// speedup vs baseline: 5.1304x; 1.0275x over previous
#include <cuda_runtime.h>
#include <cuda_fp16.h>
#include <math.h>
#include <stdint.h>

#define BB   8
#define TT   1024
#define DD   1024
#define HH   16
#define EE   64
#define FF   4096
#define BT   (BB*TT)   // 8192

// ---------------- scratch (device globals; no allocs allowed) ----------------
__device__ float  g_xn  [BT*DD];     // LN1 exact (residual for proj)
__device__ float  g_x2  [BT*DD];     // after attn residual (exact)
__device__ float  g_xn2 [BT*DD];     // LN2 exact (residual for FFN2)
__device__ __half g_xnh [BT*DD];     // LN1 f16 (GEMM A)
__device__ __half g_qkvh[BT*3*DD];   // fused QKV f16 [BT][3072]
__device__ __half g_atth[BT*DD];     // attention out f16
__device__ __half g_xn2h[BT*DD];     // LN2 f16
__device__ __half g_hh  [BT*FF];     // FFN hidden f16
__device__ __half g_wqkvt[3*DD*DD];  // [3072][1024] K-major
__device__ __half g_wpt [DD*DD];     // w_proj^T [1024][1024]
__device__ __half g_w1t [FF*DD];     // w1^T [4096][1024]
__device__ __half g_w2t [DD*FF];     // w2^T [1024][4096]

// ---------------- asm helpers ----------------
__device__ __forceinline__ void mma_f16(float* d, const unsigned* a, unsigned b0, unsigned b1) {
    asm volatile(
        "mma.sync.aligned.m16n8k16.row.col.f32.f16.f16.f32 "
        "{%0,%1,%2,%3}, {%4,%5,%6,%7}, {%8,%9}, {%0,%1,%2,%3};\n"
        : "+f"(d[0]), "+f"(d[1]), "+f"(d[2]), "+f"(d[3])
        : "r"(a[0]), "r"(a[1]), "r"(a[2]), "r"(a[3]), "r"(b0), "r"(b1));
}
// f16 accumulator variant: D/C = 2 regs (4 packed halves), 2x issue rate
__device__ __forceinline__ void mma_h16(unsigned* d, const unsigned* a, unsigned b0, unsigned b1) {
    asm volatile(
        "mma.sync.aligned.m16n8k16.row.col.f16.f16.f16.f16 "
        "{%0,%1}, {%2,%3,%4,%5}, {%6,%7}, {%0,%1};\n"
        : "+r"(d[0]), "+r"(d[1])
        : "r"(a[0]), "r"(a[1]), "r"(a[2]), "r"(a[3]), "r"(b0), "r"(b1));
}
#define LDSM4(r0,r1,r2,r3,addr) \
    asm volatile("ldmatrix.sync.aligned.m8n8.x4.shared.b16 {%0,%1,%2,%3}, [%4];" \
        : "=r"(r0), "=r"(r1), "=r"(r2), "=r"(r3) : "r"(addr))
#define LDSM4T(r0,r1,r2,r3,addr) \
    asm volatile("ldmatrix.sync.aligned.m8n8.x4.trans.shared.b16 {%0,%1,%2,%3}, [%4];" \
        : "=r"(r0), "=r"(r1), "=r"(r2), "=r"(r3) : "r"(addr))
#define CP16(sm, gm) asm volatile("cp.async.ca.shared.global [%0], [%1], 16;\n" :: "r"(sm), "l"(gm))

__device__ __forceinline__ unsigned h2u(__half2 h) { return *reinterpret_cast<unsigned*>(&h); }

// ---------------- weight prep: transpose + cvt to f16 ----------------
__global__ void transpose_cvt(const float* __restrict__ in, __half* __restrict__ out,
                              int K, int N) {
    __shared__ float tile[32][33];
    int n0 = blockIdx.x * 32, k0 = blockIdx.y * 32;
    int tx = threadIdx.x, ty = threadIdx.y;
    #pragma unroll
    for (int i = 0; i < 32; i += 8)
        tile[ty + i][tx] = in[(size_t)(k0 + ty + i) * N + n0 + tx];
    __syncthreads();
    #pragma unroll
    for (int i = 0; i < 32; i += 8)
        out[(size_t)(n0 + ty + i) * K + k0 + tx] = __float2half(tile[tx][ty + i]);
}

__global__ void qkv_w_prep(const float* __restrict__ wq, const float* __restrict__ wk,
                           const float* __restrict__ wv, __half* __restrict__ wt) {
    __shared__ float tile[32][33];
    int slot = blockIdx.z, s = slot >> 4, h = slot & 15;
    const float* w = ((s == 0) ? wq : (s == 1) ? wk : wv) + (size_t)h * DD * EE;
    __half* o = wt + (size_t)(s * DD + h * EE) * DD;
    int e0 = blockIdx.x * 32, k0 = blockIdx.y * 32;
    int tx = threadIdx.x, ty = threadIdx.y;
    #pragma unroll
    for (int i = 0; i < 32; i += 8)
        tile[ty + i][tx] = w[(size_t)(k0 + ty + i) * EE + e0 + tx];
    __syncthreads();
    #pragma unroll
    for (int i = 0; i < 32; i += 8)
        o[(size_t)(e0 + ty + i) * DD + k0 + tx] = __float2half(tile[tx][ty + i]);
}

// ---------------- LayerNorm: f32 exact + f16 outputs ----------------
__global__ void ln_kernel(const float* __restrict__ x, const float* __restrict__ g,
                          const float* __restrict__ b, float* __restrict__ y,
                          __half* __restrict__ yh) {
    int row = blockIdx.x;
    int tid = threadIdx.x;
    const float4* xr = (const float4*)(x + (size_t)row * DD);
    float4 v = xr[tid];
    float s  = v.x + v.y + v.z + v.w;
    float sq = v.x*v.x + v.y*v.y + v.z*v.z + v.w*v.w;
    #pragma unroll
    for (int m = 16; m >= 1; m >>= 1) {
        s  += __shfl_xor_sync(0xffffffffu, s,  m);
        sq += __shfl_xor_sync(0xffffffffu, sq, m);
    }
    __shared__ float ss[8], ssq[8];
    int wid = tid >> 5, lane = tid & 31;
    if (lane == 0) { ss[wid] = s; ssq[wid] = sq; }
    __syncthreads();
    s = 0.f; sq = 0.f;
    #pragma unroll
    for (int i = 0; i < 8; i++) { s += ss[i]; sq += ssq[i]; }
    float mu   = s * (1.0f / DD);
    float var  = sq * (1.0f / DD) - mu * mu;
    float rstd = rsqrtf(var + 1e-5f);
    float4 gg = ((const float4*)g)[tid];
    float4 bv = ((const float4*)b)[tid];
    float4 o;
    o.x = (v.x - mu) * rstd * gg.x + bv.x;
    o.y = (v.y - mu) * rstd * gg.y + bv.y;
    o.z = (v.z - mu) * rstd * gg.z + bv.z;
    o.w = (v.w - mu) * rstd * gg.w + bv.w;
    ((float4*)(y + (size_t)row * DD))[tid] = o;
    __half2* yh2 = (__half2*)(yh + (size_t)row * DD);
    yh2[tid * 2]     = __floats2half2_rn(o.x, o.y);
    yh2[tid * 2 + 1] = __floats2half2_rn(o.z, o.w);
}

// ---------------- f16 GEMM: multistage KB=64, f16-acc + per-stage promotion --
#define KB2  64
#define PH   72                  // smem pitch (halves)
#define STG  (128*PH)
#define NSTG 3
#define GEMM_SMEM (NSTG * 2 * STG * 2)   // 110592 B

__global__ __launch_bounds__(256) void hgemm(const __half* __restrict__ A,
        const __half* __restrict__ Bt, float* __restrict__ Cf,
        __half* __restrict__ Ch, int M, int N, int K,
        const float* __restrict__ bias, const float* __restrict__ resid, int relu) {
    extern __shared__ __half sh[];
    __half* As = sh;
    __half* Bs = sh + NSTG * STG;

    int tid = threadIdx.x, warp = tid >> 5, lane = tid & 31;
    int wm = warp >> 1, wn = warp & 1;
    int m0 = wm * 32, n0 = wn * 64;
    int rowBase = blockIdx.y * 128, colBase = blockIdx.x * 128;

    int lr = tid >> 1, lcb = (tid & 1) * 32;
    const __half* Ag = A  + (size_t)(rowBase + lr) * K + lcb;
    const __half* Bg = Bt + (size_t)(colBase + lr) * K + lcb;
    uint32_t sA = (uint32_t)__cvta_generic_to_shared(As);
    uint32_t sB = (uint32_t)__cvta_generic_to_shared(Bs);
    uint32_t cpOff = (lr * PH + lcb) * 2;

    #define HG_LOAD(k0, st) do { \
        uint32_t aS = sA + (st) * STG * 2 + cpOff; \
        uint32_t bS = sB + (st) * STG * 2 + cpOff; \
        const __half* ag = Ag + (k0); \
        const __half* bg = Bg + (k0); \
        _Pragma("unroll") \
        for (int j = 0; j < 4; j++) { \
            CP16(aS + j * 16, ag + j * 8); \
            CP16(bS + j * 16, bg + j * 8); \
        } \
    } while (0)

    float acc[2][8][4];
    #pragma unroll
    for (int mi = 0; mi < 2; mi++)
        #pragma unroll
        for (int nj = 0; nj < 8; nj++)
            #pragma unroll
            for (int t = 0; t < 4; t++) acc[mi][nj][t] = 0.f;

    int nk = K / KB2;

    HG_LOAD(0, 0);
    asm volatile("cp.async.commit_group;\n");
    HG_LOAD(KB2, 1);
    asm volatile("cp.async.commit_group;\n");

    uint32_t aF = ((m0 + (lane & 15)) * PH + (lane >> 4) * 8) * 2;
    uint32_t bF = ((n0 + (lane & 7) + ((lane >> 4) & 1) * 8) * PH + ((lane >> 3) & 1) * 8) * 2;

    for (int i = 0; i < nk; i++) {
        asm volatile("cp.async.wait_group 1;\n");
        __syncthreads();

        int ps = i + 2;
        if (ps < nk) HG_LOAD(ps * KB2, ps % NSTG);
        asm volatile("cp.async.commit_group;\n");

        int st = i % NSTG;
        uint32_t aBase = sA + st * STG * 2 + aF;
        uint32_t bBase = sB + st * STG * 2 + bF;

        // f16 accumulators for this stage (chain of 4 k16 steps)
        unsigned hacc[2][8][2];
        #pragma unroll
        for (int mi = 0; mi < 2; mi++)
            #pragma unroll
            for (int nj = 0; nj < 8; nj++) { hacc[mi][nj][0] = 0u; hacc[mi][nj][1] = 0u; }

        #pragma unroll
        for (int kk = 0; kk < 4; kk++) {
            unsigned af[2][4];
            LDSM4(af[0][0], af[0][1], af[0][2], af[0][3], aBase + kk * 32);
            LDSM4(af[1][0], af[1][1], af[1][2], af[1][3], aBase + kk * 32 + 16 * PH * 2);
            unsigned bf[8][2];
            #pragma unroll
            for (int j2 = 0; j2 < 4; j2++) {
                unsigned r0, r1, r2, r3;
                LDSM4(r0, r1, r2, r3, bBase + kk * 32 + j2 * (16 * PH * 2));
                bf[2*j2][0] = r0; bf[2*j2][1] = r1;
                bf[2*j2+1][0] = r2; bf[2*j2+1][1] = r3;
            }
            #pragma unroll
            for (int mi = 0; mi < 2; mi++)
                #pragma unroll
                for (int nj = 0; nj < 8; nj++)
                    mma_h16(hacc[mi][nj], af[mi], bf[nj][0], bf[nj][1]);
        }

        // promote stage sum into f32 accumulators
        #pragma unroll
        for (int mi = 0; mi < 2; mi++)
            #pragma unroll
            for (int nj = 0; nj < 8; nj++) {
                float2 lo = __half22float2(*reinterpret_cast<__half2*>(&hacc[mi][nj][0]));
                float2 hi = __half22float2(*reinterpret_cast<__half2*>(&hacc[mi][nj][1]));
                acc[mi][nj][0] += lo.x; acc[mi][nj][1] += lo.y;
                acc[mi][nj][2] += hi.x; acc[mi][nj][3] += hi.y;
            }
    }

    #pragma unroll
    for (int mi = 0; mi < 2; mi++) {
        int r = rowBase + m0 + mi * 16 + (lane >> 2);
        #pragma unroll
        for (int nj = 0; nj < 8; nj++) {
            int c = colBase + n0 + nj * 8 + 2 * (lane & 3);
            float v0 = acc[mi][nj][0], v1 = acc[mi][nj][1];
            float v2 = acc[mi][nj][2], v3 = acc[mi][nj][3];
            if (bias)  { v0 += bias[c]; v1 += bias[c+1]; v2 += bias[c]; v3 += bias[c+1]; }
            if (relu)  { v0 = fmaxf(v0, 0.f); v1 = fmaxf(v1, 0.f);
                         v2 = fmaxf(v2, 0.f); v3 = fmaxf(v3, 0.f); }
            if (resid) {
                const float* rr0 = resid + (size_t)r * N + c;
                const float* rr1 = resid + (size_t)(r + 8) * N + c;
                v0 += rr0[0]; v1 += rr0[1]; v2 += rr1[0]; v3 += rr1[1];
            }
            if (Cf) {
                *(float2*)&Cf[(size_t)r * N + c]       = make_float2(v0, v1);
                *(float2*)&Cf[(size_t)(r + 8) * N + c] = make_float2(v2, v3);
            }
            if (Ch) {
                *(__half2*)&Ch[(size_t)r * N + c]       = __floats2half2_rn(v0, v1);
                *(__half2*)&Ch[(size_t)(r + 8) * N + c] = __floats2half2_rn(v2, v3);
            }
        }
    }
}

// ---------------- f16 tensor-core flash attention (unchanged) ----------------
#define QP 72
__global__ __launch_bounds__(256) void flash_h(const __half* __restrict__ qkv,
                                               __half* __restrict__ attout) {
    extern __shared__ __half fsh[];
    __half* Qs = fsh;
    __half* Ks = fsh + 128 * QP;
    __half* Vs = Ks + 2 * 64 * QP;

    int tid = threadIdx.x, warp = tid >> 5, lane = tid & 31;
    int qt = blockIdx.x;
    int bh = blockIdx.y;
    int b = bh >> 4, h = bh & 15;
    const __half* Qg = qkv + (size_t)b * TT * (3 * DD) + h * EE;
    const __half* Kg = Qg + DD;
    const __half* Vg = Qg + 2 * DD;

    uint32_t sQ = (uint32_t)__cvta_generic_to_shared(Qs);
    uint32_t sK = (uint32_t)__cvta_generic_to_shared(Ks);
    uint32_t sV = (uint32_t)__cvta_generic_to_shared(Vs);

    for (int i = tid; i < 1024; i += 256) {
        int r = i >> 3, c = (i & 7) * 8;
        CP16(sQ + (r * QP + c) * 2, Qg + (size_t)(qt * 128 + r) * (3 * DD) + c);
    }
    asm volatile("cp.async.commit_group;\n");
    for (int i = tid; i < 512; i += 256) {
        int r = i >> 3, c = (i & 7) * 8;
        CP16(sK + (r * QP + c) * 2, Kg + (size_t)r * (3 * DD) + c);
        CP16(sV + (r * QP + c) * 2, Vg + (size_t)r * (3 * DD) + c);
    }
    asm volatile("cp.async.commit_group;\n");
    asm volatile("cp.async.wait_group 1;\n");
    __syncthreads();

    unsigned qf[4][4];
    {
        uint32_t qb = sQ + (((warp * 16 + (lane & 15)) * QP + (lane >> 4) * 8)) * 2;
        #pragma unroll
        for (int kk = 0; kk < 4; kk++)
            LDSM4(qf[kk][0], qf[kk][1], qf[kk][2], qf[kk][3], qb + kk * 32);
    }

    float m0r = -1e30f, m1r = -1e30f, l0 = 0.f, l1 = 0.f;
    float o[8][4];
    #pragma unroll
    for (int nj = 0; nj < 8; nj++)
        #pragma unroll
        for (int t = 0; t < 4; t++) o[nj][t] = 0.f;

    int grow0 = qt * 128 + warp * 16 + (lane >> 2);
    const float scale = 0.125f;
    int nkt = 2 * qt + 2;

    uint32_t kF = (((lane & 7) + ((lane >> 4) & 1) * 8) * QP + ((lane >> 3) & 1) * 8) * 2;
    uint32_t vF = ((((lane & 7) + ((lane >> 3) & 1) * 8)) * QP + (lane >> 4) * 8) * 2;

    for (int kt = 0; kt < nkt; kt++) {
        if (kt + 1 < nkt) {
            int st = (kt + 1) & 1;
            for (int i = tid; i < 512; i += 256) {
                int r = i >> 3, c = (i & 7) * 8;
                CP16(sK + (st * 64 * QP + r * QP + c) * 2,
                     Kg + (size_t)((kt + 1) * 64 + r) * (3 * DD) + c);
                CP16(sV + (st * 64 * QP + r * QP + c) * 2,
                     Vg + (size_t)((kt + 1) * 64 + r) * (3 * DD) + c);
            }
            asm volatile("cp.async.commit_group;\n");
            asm volatile("cp.async.wait_group 1;\n");
        } else {
            asm volatile("cp.async.wait_group 0;\n");
        }
        __syncthreads();

        uint32_t kBase = sK + (kt & 1) * 64 * QP * 2 + kF;
        uint32_t vBase = sV + (kt & 1) * 64 * QP * 2 + vF;

        float s[8][4];
        #pragma unroll
        for (int nj = 0; nj < 8; nj++)
            #pragma unroll
            for (int t = 0; t < 4; t++) s[nj][t] = 0.f;

        #pragma unroll
        for (int kk = 0; kk < 4; kk++) {
            unsigned bf[8][2];
            #pragma unroll
            for (int j2 = 0; j2 < 4; j2++) {
                unsigned r0, r1, r2, r3;
                LDSM4(r0, r1, r2, r3, kBase + kk * 32 + j2 * (16 * QP * 2));
                bf[2*j2][0] = r0; bf[2*j2][1] = r1;
                bf[2*j2+1][0] = r2; bf[2*j2+1][1] = r3;
            }
            #pragma unroll
            for (int nj = 0; nj < 8; nj++)
                mma_f16(s[nj], qf[kk], bf[nj][0], bf[nj][1]);
        }

        bool diag = (kt >= 2 * qt);
        #pragma unroll
        for (int nj = 0; nj < 8; nj++) {
            s[nj][0] *= scale; s[nj][1] *= scale;
            s[nj][2] *= scale; s[nj][3] *= scale;
            if (diag) {
                int gc = kt * 64 + nj * 8 + 2 * (lane & 3);
                if (gc     > grow0)     s[nj][0] = -1e30f;
                if (gc + 1 > grow0)     s[nj][1] = -1e30f;
                if (gc     > grow0 + 8) s[nj][2] = -1e30f;
                if (gc + 1 > grow0 + 8) s[nj][3] = -1e30f;
            }
        }

        float mx0 = -1e30f, mx1 = -1e30f;
        #pragma unroll
        for (int nj = 0; nj < 8; nj++) {
            mx0 = fmaxf(mx0, fmaxf(s[nj][0], s[nj][1]));
            mx1 = fmaxf(mx1, fmaxf(s[nj][2], s[nj][3]));
        }
        mx0 = fmaxf(mx0, __shfl_xor_sync(0xffffffffu, mx0, 1));
        mx0 = fmaxf(mx0, __shfl_xor_sync(0xffffffffu, mx0, 2));
        mx1 = fmaxf(mx1, __shfl_xor_sync(0xffffffffu, mx1, 1));
        mx1 = fmaxf(mx1, __shfl_xor_sync(0xffffffffu, mx1, 2));
        float mn0 = fmaxf(m0r, mx0), mn1 = fmaxf(m1r, mx1);
        float f0 = __expf(m0r - mn0), f1 = __expf(m1r - mn1);
        m0r = mn0; m1r = mn1;
        float rs0 = 0.f, rs1 = 0.f;
        #pragma unroll
        for (int nj = 0; nj < 8; nj++) {
            s[nj][0] = __expf(s[nj][0] - mn0); rs0 += s[nj][0];
            s[nj][1] = __expf(s[nj][1] - mn0); rs0 += s[nj][1];
            s[nj][2] = __expf(s[nj][2] - mn1); rs1 += s[nj][2];
            s[nj][3] = __expf(s[nj][3] - mn1); rs1 += s[nj][3];
        }
        rs0 += __shfl_xor_sync(0xffffffffu, rs0, 1);
        rs0 += __shfl_xor_sync(0xffffffffu, rs0, 2);
        rs1 += __shfl_xor_sync(0xffffffffu, rs1, 1);
        rs1 += __shfl_xor_sync(0xffffffffu, rs1, 2);
        l0 = l0 * f0 + rs0;
        l1 = l1 * f1 + rs1;
        #pragma unroll
        for (int nj = 0; nj < 8; nj++) {
            o[nj][0] *= f0; o[nj][1] *= f0;
            o[nj][2] *= f1; o[nj][3] *= f1;
        }

        #pragma unroll
        for (int kb = 0; kb < 4; kb++) {
            unsigned ph[4], pl[4];
            #pragma unroll
            for (int q = 0; q < 2; q++) {
                int blk = 2 * kb + q;
                __half2 h0 = __floats2half2_rn(s[blk][0], s[blk][1]);
                __half2 h1 = __floats2half2_rn(s[blk][2], s[blk][3]);
                float2 f0v = __half22float2(h0);
                float2 f1v = __half22float2(h1);
                __half2 e0 = __floats2half2_rn(s[blk][0] - f0v.x, s[blk][1] - f0v.y);
                __half2 e1 = __floats2half2_rn(s[blk][2] - f1v.x, s[blk][3] - f1v.y);
                ph[2*q]   = h2u(h0); ph[2*q+1] = h2u(h1);
                pl[2*q]   = h2u(e0); pl[2*q+1] = h2u(e1);
            }
            #pragma unroll
            for (int j2 = 0; j2 < 4; j2++) {
                unsigned b0, b1, b2, b3;
                LDSM4T(b0, b1, b2, b3, vBase + kb * (16 * QP * 2) + j2 * 32);
                mma_f16(o[2*j2],   ph, b0, b1);
                mma_f16(o[2*j2],   pl, b0, b1);
                mma_f16(o[2*j2+1], ph, b2, b3);
                mma_f16(o[2*j2+1], pl, b2, b3);
            }
        }
        __syncthreads();
    }

    float inv0 = 1.f / l0, inv1 = 1.f / l1;
    size_t row0 = (size_t)b * TT + qt * 128 + warp * 16 + (lane >> 2);
    #pragma unroll
    for (int nj = 0; nj < 8; nj++) {
        int col = h * EE + nj * 8 + 2 * (lane & 3);
        *(__half2*)&attout[row0 * DD + col] =
            __floats2half2_rn(o[nj][0] * inv0, o[nj][1] * inv0);
        *(__half2*)&attout[(row0 + 8) * DD + col] =
            __floats2half2_rn(o[nj][2] * inv1, o[nj][3] * inv1);
    }
}

// ---------------- launch ----------------
extern "C" void kernel_launch(void* const* d_in, const int* in_sizes, int n_in,
                              void* d_out, int out_size) {
    (void)in_sizes; (void)n_in; (void)out_size;
    const float* x      = (const float*)d_in[0];
    const float* wq     = (const float*)d_in[1];
    const float* wk     = (const float*)d_in[2];
    const float* wv     = (const float*)d_in[3];
    const float* w_proj = (const float*)d_in[4];
    const float* b_proj = (const float*)d_in[5];
    const float* w1     = (const float*)d_in[6];
    const float* b1     = (const float*)d_in[7];
    const float* w2     = (const float*)d_in[8];
    const float* b2     = (const float*)d_in[9];
    const float* g1     = (const float*)d_in[10];
    const float* be1    = (const float*)d_in[11];
    const float* g2     = (const float*)d_in[12];
    const float* be2    = (const float*)d_in[13];
    float* out = (float*)d_out;

    float *p_xn, *p_x2, *p_xn2;
    __half *p_xnh, *p_qkvh, *p_atth, *p_xn2h, *p_hh, *p_wqkvt, *p_wpt, *p_w1t, *p_w2t;
    cudaGetSymbolAddress((void**)&p_xn,    g_xn);
    cudaGetSymbolAddress((void**)&p_x2,    g_x2);
    cudaGetSymbolAddress((void**)&p_xn2,   g_xn2);
    cudaGetSymbolAddress((void**)&p_xnh,   g_xnh);
    cudaGetSymbolAddress((void**)&p_qkvh,  g_qkvh);
    cudaGetSymbolAddress((void**)&p_atth,  g_atth);
    cudaGetSymbolAddress((void**)&p_xn2h,  g_xn2h);
    cudaGetSymbolAddress((void**)&p_hh,    g_hh);
    cudaGetSymbolAddress((void**)&p_wqkvt, g_wqkvt);
    cudaGetSymbolAddress((void**)&p_wpt,   g_wpt);
    cudaGetSymbolAddress((void**)&p_w1t,   g_w1t);
    cudaGetSymbolAddress((void**)&p_w2t,   g_w2t);

    const int FLASH_SMEM = (128 + 4 * 64) * QP * 2;
    cudaFuncSetAttribute(hgemm,   cudaFuncAttributeMaxDynamicSharedMemorySize, GEMM_SMEM);
    cudaFuncSetAttribute(flash_h, cudaFuncAttributeMaxDynamicSharedMemorySize, FLASH_SMEM);

    // 0. weight prep (f16 + transpose)
    qkv_w_prep<<<dim3(2, 32, 48), dim3(32, 8)>>>(wq, wk, wv, p_wqkvt);
    transpose_cvt<<<dim3(32, 32),  dim3(32, 8)>>>(w_proj, p_wpt, DD, DD);
    transpose_cvt<<<dim3(128, 32), dim3(32, 8)>>>(w1, p_w1t, DD, FF);
    transpose_cvt<<<dim3(32, 128), dim3(32, 8)>>>(w2, p_w2t, FF, DD);

    // 1. LN1
    ln_kernel<<<BT, 256>>>(x, g1, be1, p_xn, p_xnh);

    // 2. fused QKV projection -> f16
    hgemm<<<dim3(24, 64), 256, GEMM_SMEM>>>(p_xnh, p_wqkvt, nullptr, p_qkvh,
                                            BT, 3 * DD, DD, nullptr, nullptr, 0);

    // 3. causal attention -> f16
    flash_h<<<dim3(TT / 128, BB * HH), 256, FLASH_SMEM>>>(p_qkvh, p_atth);

    // 4. output projection + bias + residual(xn exact) -> f32
    hgemm<<<dim3(8, 64), 256, GEMM_SMEM>>>(p_atth, p_wpt, p_x2, nullptr,
                                           BT, DD, DD, b_proj, p_xn, 0);

    // 5. LN2
    ln_kernel<<<BT, 256>>>(p_x2, g2, be2, p_xn2, p_xn2h);

    // 6. FFN1 (bias + ReLU) -> f16
    hgemm<<<dim3(32, 64), 256, GEMM_SMEM>>>(p_xn2h, p_w1t, nullptr, p_hh,
                                            BT, FF, DD, b1, nullptr, 1);

    // 7. FFN2 + bias + residual(xn2 exact) -> out f32
    hgemm<<<dim3(8, 64), 256, GEMM_SMEM>>>(p_hh, p_w2t, out, nullptr,
                                           BT, DD, FF, b2, p_xn2, 0);
}